// round 5
// baseline (speedup 1.0000x reference)
#include <cuda_runtime.h>
#include <cstdint>

#define DMODEL 256
#define D4     64
#define MAXN   100000
#define MAXE   1700000

// ---------------- scratch (static device globals, zero-init at load) --------
// INVARIANT: g_deg, g_colsum, g_colsq are all-zero at entry of every
// kernel_launch call; each call re-zeroes them before returning.
__device__ float    g_h0[(size_t)MAXN * 256];
__device__ float    g_h1[(size_t)MAXN * 512];
__device__ int      g_deg[MAXN];
__device__ int      g_rowptr[MAXN + 1];
__device__ int      g_cursor[MAXN];
__device__ int      g_esrc[MAXE];
__device__ int      g_bsum[512];
__device__ float    g_colsum[256];
__device__ float    g_colsq[256];
__device__ float    g_scale[256];
__device__ float    g_shift[256];

// ---------------- helpers ----------------------------------------------------
__device__ __forceinline__ uint32_t f2tf(float f) {
    uint32_t r;
    asm("cvt.rna.tf32.f32 %0, %1;" : "=r"(r) : "f"(f));
    return r;
}

__device__ __forceinline__ void mma_tf32(float* c, const uint32_t* a, const uint32_t* b) {
    asm volatile(
        "mma.sync.aligned.m16n8k8.row.col.f32.tf32.tf32.f32 "
        "{%0,%1,%2,%3}, {%4,%5,%6,%7}, {%8,%9}, {%0,%1,%2,%3};"
        : "+f"(c[0]), "+f"(c[1]), "+f"(c[2]), "+f"(c[3])
        : "r"(a[0]), "r"(a[1]), "r"(a[2]), "r"(a[3]), "r"(b[0]), "r"(b[1]));
}

// Per-block int64-vs-int32 sniff: int64 idx < 2^32 -> high words all zero.
__device__ __forceinline__ int block_is64(const void* idxbuf, int E) {
    __shared__ int s_bad;
    if (threadIdx.x == 0) s_bad = 0;
    __syncthreads();
    int words = E >> 1; if (words > 64) words = 64;
    if (threadIdx.x < (unsigned)words) {
        unsigned long long w = ((const unsigned long long*)idxbuf)[threadIdx.x];
        if ((w >> 32) != 0ull) atomicOr(&s_bad, 1);
    }
    __syncthreads();
    return !s_bad;
}

// ---------------- launch 0: histogram of dst ---------------------------------
__global__ void k_hist(const void* __restrict__ dstb, int E) {
    int is64 = block_is64(dstb, E);
    int e = blockIdx.x * blockDim.x + threadIdx.x;
    if (e >= E) return;
    int d = is64 ? (int)((const long long*)dstb)[e] : ((const int*)dstb)[e];
    atomicAdd(&g_deg[d], 1);
}

// ---------------- launch 1: per-block degree sums ----------------------------
__global__ __launch_bounds__(512)
void k_chunksum(int n) {
    __shared__ int sm[512];
    int t = threadIdx.x;
    int i = blockIdx.x * 512 + t;
    sm[t] = (i < n) ? g_deg[i] : 0;
    __syncthreads();
    #pragma unroll
    for (int off = 256; off > 0; off >>= 1) {
        if (t < off) sm[t] += sm[t + off];
        __syncthreads();
    }
    if (t == 0) g_bsum[blockIdx.x] = sm[0];
}

// ---------------- launch 2: scan + write rowptr/cursor + zero deg ------------
__global__ __launch_bounds__(512)
void k_scanwrite(int n) {
    __shared__ int red[512];
    __shared__ int sm[512];
    int t = threadIdx.x, b = blockIdx.x;
    int part = 0;
    for (int i = t; i < b; i += 512) part += g_bsum[i];
    red[t] = part;
    __syncthreads();
    #pragma unroll
    for (int off = 256; off > 0; off >>= 1) {
        if (t < off) red[t] += red[t + off];
        __syncthreads();
    }
    int base = red[0];

    int i = b * 512 + t;
    int v = (i < n) ? g_deg[i] : 0;
    sm[t] = v;
    __syncthreads();
    for (int off = 1; off < 512; off <<= 1) {
        int x = (t >= off) ? sm[t - off] : 0;
        __syncthreads();
        sm[t] += x;
        __syncthreads();
    }
    if (i < n) {
        int excl = base + sm[t] - v;
        g_rowptr[i] = excl;
        g_cursor[i] = excl;
        g_deg[i] = 0;                         // restore invariant
        if (i == n - 1) g_rowptr[n] = excl + v;
    }
}

// ---------------- launch 3: bucket edges by dst ------------------------------
__global__ void k_reorder(const void* __restrict__ srcb, const void* __restrict__ dstb, int E) {
    int is64 = block_is64(dstb, E);
    int e = blockIdx.x * blockDim.x + threadIdx.x;
    if (e >= E) return;
    int s, d;
    if (is64) {
        s = (int)((const long long*)srcb)[e];
        d = (int)((const long long*)dstb)[e];
    } else {
        s = ((const int*)srcb)[e];
        d = ((const int*)dstb)[e];
    }
    int pos = atomicAdd(&g_cursor[d], 1);
    g_esrc[pos] = s;
}

// ---------------- launch 4: gather-sum, 2 warps/node, unroll 4 ---------------
__global__ __launch_bounds__(256)
void k_gather(const float4* __restrict__ x, const float* __restrict__ eps, int n) {
    int gw   = (int)((blockIdx.x * blockDim.x + threadIdx.x) >> 5);
    int lane = threadIdx.x & 31;
    int node = gw >> 1;
    if (node >= n) return;
    int col   = ((gw & 1) << 5) + lane;
    int start = g_rowptr[node], end = g_rowptr[node + 1];

    float4 a0 = make_float4(0.f, 0.f, 0.f, 0.f);
    float4 a1 = make_float4(0.f, 0.f, 0.f, 0.f);
    float4 a2 = make_float4(0.f, 0.f, 0.f, 0.f);
    float4 a3 = make_float4(0.f, 0.f, 0.f, 0.f);

    int i = start;
    for (; i + 4 <= end; i += 4) {
        int s0 = __ldg(&g_esrc[i]);
        int s1 = __ldg(&g_esrc[i + 1]);
        int s2 = __ldg(&g_esrc[i + 2]);
        int s3 = __ldg(&g_esrc[i + 3]);
        float4 v0 = __ldg(x + (size_t)s0 * D4 + col);
        float4 v1 = __ldg(x + (size_t)s1 * D4 + col);
        float4 v2 = __ldg(x + (size_t)s2 * D4 + col);
        float4 v3 = __ldg(x + (size_t)s3 * D4 + col);
        a0.x += v0.x; a0.y += v0.y; a0.z += v0.z; a0.w += v0.w;
        a1.x += v1.x; a1.y += v1.y; a1.z += v1.z; a1.w += v1.w;
        a2.x += v2.x; a2.y += v2.y; a2.z += v2.z; a2.w += v2.w;
        a3.x += v3.x; a3.y += v3.y; a3.z += v3.z; a3.w += v3.w;
    }
    for (; i < end; i++) {
        int s0 = __ldg(&g_esrc[i]);
        float4 v0 = __ldg(x + (size_t)s0 * D4 + col);
        a0.x += v0.x; a0.y += v0.y; a0.z += v0.z; a0.w += v0.w;
    }
    a0.x += a1.x + a2.x + a3.x;
    a0.y += a1.y + a2.y + a3.y;
    a0.z += a1.z + a2.z + a3.z;
    a0.w += a1.w + a2.w + a3.w;

    float sc = 1.0f + __ldg(eps);
    float4 xv = __ldg(x + (size_t)node * D4 + col);
    ((float4*)g_h0)[(size_t)node * D4 + col] =
        make_float4(fmaf(sc, xv.x, a0.x), fmaf(sc, xv.y, a0.y),
                    fmaf(sc, xv.z, a0.z), fmaf(sc, xv.w, a0.w));
}

// ---------------- tf32 GEMM: EXACT round-1 version (measured 253us @ gemm1) --
// Block tile 128x64, BK=32, 8 warps (4x2), warp tile 32x32 of m16n8k8 frags.
template <int K, int NT, bool RELU, bool STATS>
__global__ __launch_bounds__(256, 2)
void k_gemm(const float* __restrict__ A, const float* __restrict__ B,
            const float* __restrict__ bias, float* __restrict__ C, int M) {
    __shared__ uint32_t As[128 * 36];   // stride 36 -> (4*gid + tig) conflict-free
    __shared__ uint32_t Bs[32 * 72];    // stride 72 -> (8*tig + gid) conflict-free
    __shared__ float s_sum[64];
    __shared__ float s_sq[64];

    const int tid  = threadIdx.x;
    const int warp = tid >> 5, lane = tid & 31;
    const int wm = warp >> 1, wn = warp & 1;          // 4x2 warp grid
    const int gid = lane >> 2, tig = lane & 3;
    const int bm = blockIdx.y, bn = blockIdx.x;
    const int row0 = bm * 128;

    float acc[2][4][4];
    #pragma unroll
    for (int i = 0; i < 2; i++)
        #pragma unroll
        for (int j = 0; j < 4; j++)
            #pragma unroll
            for (int l = 0; l < 4; l++) acc[i][j][l] = 0.f;

    const int KT = K / 32;
    for (int kt = 0; kt < KT; ++kt) {
        // load A tile: 128x32 floats = 1024 float4, 4 per thread
        #pragma unroll
        for (int j = 0; j < 4; j++) {
            int idx = tid + j * 256;
            int r = idx >> 3, c4 = idx & 7;
            int grow = row0 + r;
            float4 v = make_float4(0.f, 0.f, 0.f, 0.f);
            if (grow < M)
                v = *(const float4*)(A + (size_t)grow * K + kt * 32 + c4 * 4);
            uint4 t;
            t.x = f2tf(v.x); t.y = f2tf(v.y); t.z = f2tf(v.z); t.w = f2tf(v.w);
            *(uint4*)(&As[r * 36 + c4 * 4]) = t;
        }
        // load B tile: 32x64 floats = 512 float4, 2 per thread
        #pragma unroll
        for (int j = 0; j < 2; j++) {
            int idx = tid + j * 256;
            int r = idx >> 4, c4 = idx & 15;
            float4 v = *(const float4*)(B + (size_t)(kt * 32 + r) * NT + bn * 64 + c4 * 4);
            uint4 t;
            t.x = f2tf(v.x); t.y = f2tf(v.y); t.z = f2tf(v.z); t.w = f2tf(v.w);
            *(uint4*)(&Bs[r * 72 + c4 * 4]) = t;
        }
        __syncthreads();

        #pragma unroll
        for (int kk = 0; kk < 4; kk++) {
            uint32_t a[2][4], b[4][2];
            #pragma unroll
            for (int mf = 0; mf < 2; mf++) {
                int rb = wm * 32 + mf * 16 + gid;
                a[mf][0] = As[(rb    ) * 36 + kk * 8 + tig    ];
                a[mf][1] = As[(rb + 8) * 36 + kk * 8 + tig    ];
                a[mf][2] = As[(rb    ) * 36 + kk * 8 + tig + 4];
                a[mf][3] = As[(rb + 8) * 36 + kk * 8 + tig + 4];
            }
            #pragma unroll
            for (int nf = 0; nf < 4; nf++) {
                int col = wn * 32 + nf * 8 + gid;
                b[nf][0] = Bs[(kk * 8 + tig    ) * 72 + col];
                b[nf][1] = Bs[(kk * 8 + tig + 4) * 72 + col];
            }
            #pragma unroll
            for (int mf = 0; mf < 2; mf++)
                #pragma unroll
                for (int nf = 0; nf < 4; nf++)
                    mma_tf32(acc[mf][nf], a[mf], b[nf]);
        }
        __syncthreads();
    }

    // -------- epilogue: bias (+relu) (+BN stats) --------
    float lsum[8], lsq[8];
    #pragma unroll
    for (int i = 0; i < 8; i++) { lsum[i] = 0.f; lsq[i] = 0.f; }

    #pragma unroll
    for (int mf = 0; mf < 2; mf++) {
        #pragma unroll
        for (int h = 0; h < 2; h++) {
            int row = row0 + wm * 32 + mf * 16 + gid + h * 8;
            bool ok = row < M;
            #pragma unroll
            for (int nf = 0; nf < 4; nf++) {
                int col = bn * 64 + wn * 32 + nf * 8 + 2 * tig;
                float v0 = acc[mf][nf][2 * h + 0] + __ldg(&bias[col]);
                float v1 = acc[mf][nf][2 * h + 1] + __ldg(&bias[col + 1]);
                if (RELU) { v0 = fmaxf(v0, 0.f); v1 = fmaxf(v1, 0.f); }
                if (ok) {
                    *(float2*)(C + (size_t)row * NT + col) = make_float2(v0, v1);
                    if (STATS) {
                        lsum[nf * 2    ] += v0; lsq[nf * 2    ] += v0 * v0;
                        lsum[nf * 2 + 1] += v1; lsq[nf * 2 + 1] += v1 * v1;
                    }
                }
            }
        }
    }

    if (STATS) {
        if (tid < 64) { s_sum[tid] = 0.f; s_sq[tid] = 0.f; }
        __syncthreads();
        #pragma unroll
        for (int nf = 0; nf < 4; nf++)
            #pragma unroll
            for (int j = 0; j < 2; j++) {
                int lc = wn * 32 + nf * 8 + 2 * tig + j;
                atomicAdd(&s_sum[lc], lsum[nf * 2 + j]);
                atomicAdd(&s_sq[lc],  lsq[nf * 2 + j]);
            }
        __syncthreads();
        if (tid < 64) {
            atomicAdd(&g_colsum[bn * 64 + tid], s_sum[tid]);
            atomicAdd(&g_colsq[bn * 64 + tid],  s_sq[tid]);
        }
    }
}

// ---------------- BN finalize (re-zeroes accumulators) -----------------------
__global__ void k_finalize(const float* __restrict__ gamma,
                           const float* __restrict__ beta, float invN) {
    int c = threadIdx.x;
    float mean = g_colsum[c] * invN;
    float var  = g_colsq[c] * invN - mean * mean;
    var = fmaxf(var, 0.f);
    float inv  = rsqrtf(var + 1e-5f);
    float sc   = gamma[c] * inv;
    g_scale[c] = sc;
    g_shift[c] = beta[c] - mean * sc;
    g_colsum[c] = 0.f;
    g_colsq[c]  = 0.f;
}

// ---------------- BN apply ---------------------------------------------------
__global__ void k_bn(float4* __restrict__ out, int n4) {
    const float4* sc4 = (const float4*)g_scale;
    const float4* sh4 = (const float4*)g_shift;
    for (int i = blockIdx.x * blockDim.x + threadIdx.x; i < n4; i += gridDim.x * blockDim.x) {
        int c4 = i & (D4 - 1);
        float4 sc = sc4[c4], sh = sh4[c4];
        float4 v = out[i];
        v.x = fmaf(v.x, sc.x, sh.x);
        v.y = fmaf(v.y, sc.y, sh.y);
        v.z = fmaf(v.z, sc.z, sh.z);
        v.w = fmaf(v.w, sc.w, sh.w);
        out[i] = v;
    }
}

// ---------------- launch -----------------------------------------------------
extern "C" void kernel_launch(void* const* d_in, const int* in_sizes, int n_in,
                              void* d_out, int out_size) {
    const float* x     = (const float*)d_in[0];
    const void*  src   = d_in[1];
    const void*  dst   = d_in[2];
    const float* eps   = (const float*)d_in[3];
    const float* W1    = (const float*)d_in[4];
    const float* b1    = (const float*)d_in[5];
    const float* W2    = (const float*)d_in[6];
    const float* b2    = (const float*)d_in[7];
    const float* gamma = (const float*)d_in[8];
    const float* beta  = (const float*)d_in[9];
    float* out = (float*)d_out;

    int M  = in_sizes[0] / DMODEL;
    int E  = in_sizes[1];
    int n4 = M * D4;

    void* ph0 = nullptr; cudaGetSymbolAddress(&ph0, g_h0);
    void* ph1 = nullptr; cudaGetSymbolAddress(&ph1, g_h1);

    int NSB = (M + 511) / 512;

    k_hist<<<(E + 255) / 256, 256>>>(dst, E);          // 0
    k_chunksum<<<NSB, 512>>>(M);                       // 1
    k_scanwrite<<<NSB, 512>>>(M);                      // 2
    k_reorder<<<(E + 255) / 256, 256>>>(src, dst, E);  // 3  <- profiled
    k_gather<<<(M * 64 + 255) / 256, 256>>>((const float4*)x, eps, M);

    int mt = (M + 127) / 128;
    k_gemm<256, 512, true,  false><<<dim3(8, mt), 256>>>((const float*)ph0, W1, b1, (float*)ph1, M);
    k_gemm<512, 256, false, true ><<<dim3(4, mt), 256>>>((const float*)ph1, W2, b2, out, M);

    k_finalize<<<1, 256>>>(gamma, beta, 1.0f / (float)M);
    k_bn<<<2048, 256>>>((float4*)out, n4);
}

// round 9
// speedup vs baseline: 1.7851x; 1.7851x over previous
#include <cuda_runtime.h>
#include <cuda_fp16.h>
#include <cstdint>

#define DMODEL 256
#define D4     64
#define MAXN   100000
#define MAXE   1700000

// ---------------- scratch (static device globals, zero-init at load) --------
// INVARIANT: g_deg, g_colsum, g_colsq are all-zero at entry of every
// kernel_launch call; each call re-zeroes them before returning.
__device__ float    g_h0[(size_t)MAXN * 256];
__device__ float    g_h1[(size_t)MAXN * 512];
__device__ __half   g_Bh1[512 * 256];   // W1^T in fp16: [n<512][k<256]
__device__ __half   g_Bh2[256 * 512];   // W2^T in fp16: [n<256][k<512]
__device__ int      g_deg[MAXN];
__device__ int      g_rowptr[MAXN + 1];
__device__ int      g_cursor[MAXN];
__device__ int      g_esrc[MAXE];
__device__ int      g_bsum[512];
__device__ float    g_colsum[256];
__device__ float    g_colsq[256];
__device__ float    g_scale[256];
__device__ float    g_shift[256];

// ---------------- helpers ----------------------------------------------------
__device__ __forceinline__ uint32_t smem_u32(const void* p) {
    uint32_t a;
    asm("{ .reg .u64 t; cvta.to.shared.u64 t, %1; cvt.u32.u64 %0, t; }" : "=r"(a) : "l"(p));
    return a;
}

__device__ __forceinline__ uint32_t h2u(half2 h) {
    union { half2 h; uint32_t u; } cvt;
    cvt.h = h;
    return cvt.u;
}

// fp16 tensor-core MMA, fp32 accumulate
__device__ __forceinline__ void mma_f16(float* c, const uint32_t* a, const uint32_t* b) {
    asm volatile(
        "mma.sync.aligned.m16n8k16.row.col.f32.f16.f16.f32 "
        "{%0,%1,%2,%3}, {%4,%5,%6,%7}, {%8,%9}, {%0,%1,%2,%3};"
        : "+f"(c[0]), "+f"(c[1]), "+f"(c[2]), "+f"(c[3])
        : "r"(a[0]), "r"(a[1]), "r"(a[2]), "r"(a[3]), "r"(b[0]), "r"(b[1]));
}

__device__ __forceinline__ void ldsm_x4(uint32_t& r0, uint32_t& r1, uint32_t& r2,
                                        uint32_t& r3, uint32_t addr) {
    asm volatile("ldmatrix.sync.aligned.m8n8.x4.shared.b16 {%0,%1,%2,%3}, [%4];"
                 : "=r"(r0), "=r"(r1), "=r"(r2), "=r"(r3) : "r"(addr));
}

// Per-block int64-vs-int32 sniff: int64 idx < 2^32 -> high words all zero.
__device__ __forceinline__ int block_is64(const void* idxbuf, int E) {
    __shared__ int s_bad;
    if (threadIdx.x == 0) s_bad = 0;
    __syncthreads();
    int words = E >> 1; if (words > 64) words = 64;
    if (threadIdx.x < (unsigned)words) {
        unsigned long long w = ((const unsigned long long*)idxbuf)[threadIdx.x];
        if ((w >> 32) != 0ull) atomicOr(&s_bad, 1);
    }
    __syncthreads();
    return !s_bad;
}

// ---------------- CSR aggregation (unchanged from R5 passing version) --------
__global__ void k_hist(const void* __restrict__ dstb, int E) {
    int is64 = block_is64(dstb, E);
    int e = blockIdx.x * blockDim.x + threadIdx.x;
    if (e >= E) return;
    int d = is64 ? (int)((const long long*)dstb)[e] : ((const int*)dstb)[e];
    atomicAdd(&g_deg[d], 1);
}

__global__ __launch_bounds__(512)
void k_chunksum(int n) {
    __shared__ int sm[512];
    int t = threadIdx.x;
    int i = blockIdx.x * 512 + t;
    sm[t] = (i < n) ? g_deg[i] : 0;
    __syncthreads();
    #pragma unroll
    for (int off = 256; off > 0; off >>= 1) {
        if (t < off) sm[t] += sm[t + off];
        __syncthreads();
    }
    if (t == 0) g_bsum[blockIdx.x] = sm[0];
}

__global__ __launch_bounds__(512)
void k_scanwrite(int n) {
    __shared__ int red[512];
    __shared__ int sm[512];
    int t = threadIdx.x, b = blockIdx.x;
    int part = 0;
    for (int i = t; i < b; i += 512) part += g_bsum[i];
    red[t] = part;
    __syncthreads();
    #pragma unroll
    for (int off = 256; off > 0; off >>= 1) {
        if (t < off) red[t] += red[t + off];
        __syncthreads();
    }
    int base = red[0];

    int i = b * 512 + t;
    int v = (i < n) ? g_deg[i] : 0;
    sm[t] = v;
    __syncthreads();
    for (int off = 1; off < 512; off <<= 1) {
        int x = (t >= off) ? sm[t - off] : 0;
        __syncthreads();
        sm[t] += x;
        __syncthreads();
    }
    if (i < n) {
        int excl = base + sm[t] - v;
        g_rowptr[i] = excl;
        g_cursor[i] = excl;
        g_deg[i] = 0;                         // restore invariant
        if (i == n - 1) g_rowptr[n] = excl + v;
    }
}

__global__ void k_reorder(const void* __restrict__ srcb, const void* __restrict__ dstb, int E) {
    int is64 = block_is64(dstb, E);
    int e = blockIdx.x * blockDim.x + threadIdx.x;
    if (e >= E) return;
    int s, d;
    if (is64) {
        s = (int)((const long long*)srcb)[e];
        d = (int)((const long long*)dstb)[e];
    } else {
        s = ((const int*)srcb)[e];
        d = ((const int*)dstb)[e];
    }
    int pos = atomicAdd(&g_cursor[d], 1);
    g_esrc[pos] = s;
}

__global__ __launch_bounds__(256)
void k_gather(const float4* __restrict__ x, const float* __restrict__ eps, int n) {
    int gw   = (int)((blockIdx.x * blockDim.x + threadIdx.x) >> 5);
    int lane = threadIdx.x & 31;
    int node = gw >> 1;
    if (node >= n) return;
    int col   = ((gw & 1) << 5) + lane;
    int start = g_rowptr[node], end = g_rowptr[node + 1];

    float4 a0 = make_float4(0.f, 0.f, 0.f, 0.f);
    float4 a1 = make_float4(0.f, 0.f, 0.f, 0.f);
    float4 a2 = make_float4(0.f, 0.f, 0.f, 0.f);
    float4 a3 = make_float4(0.f, 0.f, 0.f, 0.f);

    int i = start;
    for (; i + 4 <= end; i += 4) {
        int s0 = __ldg(&g_esrc[i]);
        int s1 = __ldg(&g_esrc[i + 1]);
        int s2 = __ldg(&g_esrc[i + 2]);
        int s3 = __ldg(&g_esrc[i + 3]);
        float4 v0 = __ldg(x + (size_t)s0 * D4 + col);
        float4 v1 = __ldg(x + (size_t)s1 * D4 + col);
        float4 v2 = __ldg(x + (size_t)s2 * D4 + col);
        float4 v3 = __ldg(x + (size_t)s3 * D4 + col);
        a0.x += v0.x; a0.y += v0.y; a0.z += v0.z; a0.w += v0.w;
        a1.x += v1.x; a1.y += v1.y; a1.z += v1.z; a1.w += v1.w;
        a2.x += v2.x; a2.y += v2.y; a2.z += v2.z; a2.w += v2.w;
        a3.x += v3.x; a3.y += v3.y; a3.z += v3.z; a3.w += v3.w;
    }
    for (; i < end; i++) {
        int s0 = __ldg(&g_esrc[i]);
        float4 v0 = __ldg(x + (size_t)s0 * D4 + col);
        a0.x += v0.x; a0.y += v0.y; a0.z += v0.z; a0.w += v0.w;
    }
    a0.x += a1.x + a2.x + a3.x;
    a0.y += a1.y + a2.y + a3.y;
    a0.z += a1.z + a2.z + a3.z;
    a0.w += a1.w + a2.w + a3.w;

    float sc = 1.0f + __ldg(eps);
    float4 xv = __ldg(x + (size_t)node * D4 + col);
    ((float4*)g_h0)[(size_t)node * D4 + col] =
        make_float4(fmaf(sc, xv.x, a0.x), fmaf(sc, xv.y, a0.y),
                    fmaf(sc, xv.z, a0.z), fmaf(sc, xv.w, a0.w));
}

// ---------------- weight pre-transform: W[k][n] fp32 -> Bh[n][k] fp16 --------
__global__ void k_prepBH(const float* __restrict__ W, __half* __restrict__ Bh,
                         int KK, int NT) {
    int i = blockIdx.x * blockDim.x + threadIdx.x;
    if (i >= KK * NT) return;
    int k = i / NT, n = i - k * NT;
    Bh[(size_t)n * KK + k] = __float2half_rn(W[i]);
}

// ---------------- fp16 tensor-core GEMM --------------------------------------
// C[M,NT] = A[M,K] @ W[K,NT] + bias.  Block tile 128x128, BK=32, 8 warps (2x4),
// warp tile 64x32 (mf=4, nf=4) of m16n8k16 frags, ldmatrix.x4 operand loads.
// Smem rows padded to 40 halves (80B): (5r+c) mod 8 distinct -> LDSM conflict-free.
template <int K, int NT, bool RELU, bool STATS>
__global__ __launch_bounds__(256, 2)
void k_hgemm(const float* __restrict__ A, const __half* __restrict__ Bh,
             const float* __restrict__ bias, float* __restrict__ C, int M) {
    constexpr int KT = K / 32;
    __shared__ __align__(16) __half As[128 * 40];
    __shared__ __align__(16) __half Bs[128 * 40];
    __shared__ float s_sum[128];
    __shared__ float s_sq[128];

    const int tid  = threadIdx.x;
    const int warp = tid >> 5, lane = tid & 31;
    const int wm = warp >> 2, wn = warp & 3;          // 2x4 warp grid
    const int row0 = blockIdx.y * 128, n0 = blockIdx.x * 128;

    const uint32_t sAs = smem_u32(As);
    const uint32_t sBs = smem_u32(Bs);

    float acc[4][4][4];
    #pragma unroll
    for (int i = 0; i < 4; i++)
        #pragma unroll
        for (int j = 0; j < 4; j++)
            #pragma unroll
            for (int l = 0; l < 4; l++) acc[i][j][l] = 0.f;

    // ldmatrix lane->address components
    const int a_row = lane & 15, a_kb = lane >> 4;                 // A: row, k-block
    const int b_n   = (lane & 7) + ((lane >> 4) << 3);             // B: n-row
    const int b_kb  = (lane >> 3) & 1;                             // B: k-block

    const int sr  = tid >> 1, seg = tid & 1;   // staging: row, 16-element segment

    for (int kt = 0; kt < KT; ++kt) {
        // ---- stage A: 128x32 fp32 -> fp16 ----
        {
            uint4 w0, w1;
            if (row0 + sr < M) {
                const float4* pa = (const float4*)(A + (size_t)(row0 + sr) * K + kt * 32 + seg * 16);
                float4 v0 = __ldg(pa), v1 = __ldg(pa + 1), v2 = __ldg(pa + 2), v3 = __ldg(pa + 3);
                w0 = make_uint4(h2u(__floats2half2_rn(v0.x, v0.y)),
                                h2u(__floats2half2_rn(v0.z, v0.w)),
                                h2u(__floats2half2_rn(v1.x, v1.y)),
                                h2u(__floats2half2_rn(v1.z, v1.w)));
                w1 = make_uint4(h2u(__floats2half2_rn(v2.x, v2.y)),
                                h2u(__floats2half2_rn(v2.z, v2.w)),
                                h2u(__floats2half2_rn(v3.x, v3.y)),
                                h2u(__floats2half2_rn(v3.z, v3.w)));
            } else {
                w0 = make_uint4(0u, 0u, 0u, 0u);
                w1 = make_uint4(0u, 0u, 0u, 0u);
            }
            uint4* dst = (uint4*)&As[sr * 40 + seg * 16];
            dst[0] = w0; dst[1] = w1;
        }
        // ---- stage B: 128x32 fp16 copy ----
        {
            const uint4* pb = (const uint4*)(Bh + (size_t)(n0 + sr) * K + kt * 32 + seg * 16);
            uint4 w0 = __ldg(pb), w1 = __ldg(pb + 1);
            uint4* dst = (uint4*)&Bs[sr * 40 + seg * 16];
            dst[0] = w0; dst[1] = w1;
        }
        __syncthreads();

        #pragma unroll
        for (int kk = 0; kk < 2; kk++) {
            uint32_t a[4][4], b[4][2];
            #pragma unroll
            for (int mf = 0; mf < 4; mf++) {
                uint32_t addr = sAs + ((wm * 64 + mf * 16 + a_row) * 40 + kk * 16 + a_kb * 8) * 2;
                ldsm_x4(a[mf][0], a[mf][1], a[mf][2], a[mf][3], addr);
            }
            #pragma unroll
            for (int p = 0; p < 2; p++) {
                uint32_t addr = sBs + ((wn * 32 + p * 16 + b_n) * 40 + kk * 16 + b_kb * 8) * 2;
                uint32_t r0, r1, r2, r3;
                ldsm_x4(r0, r1, r2, r3, addr);
                b[2 * p][0] = r0; b[2 * p][1] = r1;
                b[2 * p + 1][0] = r2; b[2 * p + 1][1] = r3;
            }
            #pragma unroll
            for (int mf = 0; mf < 4; mf++)
                #pragma unroll
                for (int nf = 0; nf < 4; nf++)
                    mma_f16(acc[mf][nf], a[mf], b[nf]);
        }
        __syncthreads();
    }

    // -------- epilogue: bias (+relu) (+BN stats) --------
    const int quad = lane >> 2, tq = lane & 3;
    float lsum[8], lsq[8];
    #pragma unroll
    for (int i = 0; i < 8; i++) { lsum[i] = 0.f; lsq[i] = 0.f; }

    #pragma unroll
    for (int mf = 0; mf < 4; mf++) {
        #pragma unroll
        for (int h = 0; h < 2; h++) {
            int row = row0 + wm * 64 + mf * 16 + quad + h * 8;
            bool ok = row < M;
            #pragma unroll
            for (int nf = 0; nf < 4; nf++) {
                int col = n0 + wn * 32 + nf * 8 + 2 * tq;
                float v0 = acc[mf][nf][2 * h + 0] + __ldg(&bias[col]);
                float v1 = acc[mf][nf][2 * h + 1] + __ldg(&bias[col + 1]);
                if (RELU) { v0 = fmaxf(v0, 0.f); v1 = fmaxf(v1, 0.f); }
                if (ok) {
                    *(float2*)(C + (size_t)row * NT + col) = make_float2(v0, v1);
                    if (STATS) {
                        lsum[nf * 2    ] += v0; lsq[nf * 2    ] += v0 * v0;
                        lsum[nf * 2 + 1] += v1; lsq[nf * 2 + 1] += v1 * v1;
                    }
                }
            }
        }
    }

    if (STATS) {
        if (tid < 128) { s_sum[tid] = 0.f; s_sq[tid] = 0.f; }
        __syncthreads();
        #pragma unroll
        for (int nf = 0; nf < 4; nf++)
            #pragma unroll
            for (int j = 0; j < 2; j++) {
                int lc = wn * 32 + nf * 8 + 2 * tq + j;
                atomicAdd(&s_sum[lc], lsum[nf * 2 + j]);
                atomicAdd(&s_sq[lc],  lsq[nf * 2 + j]);
            }
        __syncthreads();
        if (tid < 128) {
            atomicAdd(&g_colsum[n0 + tid], s_sum[tid]);
            atomicAdd(&g_colsq[n0 + tid],  s_sq[tid]);
        }
    }
}

// ---------------- BN finalize (re-zeroes accumulators) -----------------------
__global__ void k_finalize(const float* __restrict__ gamma,
                           const float* __restrict__ beta, float invN) {
    int c = threadIdx.x;
    float mean = g_colsum[c] * invN;
    float var  = g_colsq[c] * invN - mean * mean;
    var = fmaxf(var, 0.f);
    float inv  = rsqrtf(var + 1e-5f);
    float sc   = gamma[c] * inv;
    g_scale[c] = sc;
    g_shift[c] = beta[c] - mean * sc;
    g_colsum[c] = 0.f;
    g_colsq[c]  = 0.f;
}

// ---------------- BN apply ---------------------------------------------------
__global__ void k_bn(float4* __restrict__ out, int n4) {
    const float4* sc4 = (const float4*)g_scale;
    const float4* sh4 = (const float4*)g_shift;
    for (int i = blockIdx.x * blockDim.x + threadIdx.x; i < n4; i += gridDim.x * blockDim.x) {
        int c4 = i & (D4 - 1);
        float4 sc = sc4[c4], sh = sh4[c4];
        float4 v = out[i];
        v.x = fmaf(v.x, sc.x, sh.x);
        v.y = fmaf(v.y, sc.y, sh.y);
        v.z = fmaf(v.z, sc.z, sh.z);
        v.w = fmaf(v.w, sc.w, sh.w);
        out[i] = v;
    }
}

// ---------------- launch -----------------------------------------------------
extern "C" void kernel_launch(void* const* d_in, const int* in_sizes, int n_in,
                              void* d_out, int out_size) {
    const float* x     = (const float*)d_in[0];
    const void*  src   = d_in[1];
    const void*  dst   = d_in[2];
    const float* eps   = (const float*)d_in[3];
    const float* W1    = (const float*)d_in[4];
    const float* b1    = (const float*)d_in[5];
    const float* W2    = (const float*)d_in[6];
    const float* b2    = (const float*)d_in[7];
    const float* gamma = (const float*)d_in[8];
    const float* beta  = (const float*)d_in[9];
    float* out = (float*)d_out;

    int M  = in_sizes[0] / DMODEL;
    int E  = in_sizes[1];
    int n4 = M * D4;

    void* ph0  = nullptr; cudaGetSymbolAddress(&ph0,  g_h0);
    void* ph1  = nullptr; cudaGetSymbolAddress(&ph1,  g_h1);
    void* pbh1 = nullptr; cudaGetSymbolAddress(&pbh1, g_Bh1);
    void* pbh2 = nullptr; cudaGetSymbolAddress(&pbh2, g_Bh2);

    int NSB = (M + 511) / 512;

    k_hist<<<(E + 255) / 256, 256>>>(dst, E);          // 0
    k_chunksum<<<NSB, 512>>>(M);                       // 1
    k_scanwrite<<<NSB, 512>>>(M);                      // 2
    k_reorder<<<(E + 255) / 256, 256>>>(src, dst, E);  // 3  <- profiled
    k_gather<<<(M * 64 + 255) / 256, 256>>>((const float4*)x, eps, M);

    k_prepBH<<<(256 * 512 + 255) / 256, 256>>>(W1, (__half*)pbh1, 256, 512);
    k_prepBH<<<(512 * 256 + 255) / 256, 256>>>(W2, (__half*)pbh2, 512, 256);

    int mt = (M + 127) / 128;
    k_hgemm<256, 512, true,  false><<<dim3(4, mt), 256>>>(
        (const float*)ph0, (const __half*)pbh1, b1, (float*)ph1, M);
    k_hgemm<512, 256, false, true ><<<dim3(2, mt), 256>>>(
        (const float*)ph1, (const __half*)pbh2, b2, out, M);

    k_finalize<<<1, 256>>>(gamma, beta, 1.0f / (float)M);
    k_bn<<<2048, 256>>>((float4*)out, n4);
}

// round 10
// speedup vs baseline: 2.3496x; 1.3162x over previous
#include <cuda_runtime.h>
#include <cuda_fp16.h>
#include <cstdint>

#define DMODEL 256
#define D4     64
#define MAXN   100000
#define MAXE   1700000

// ---------------- scratch (static device globals, zero-init at load) --------
// INVARIANT: g_deg, g_colsum, g_colsq are all-zero at entry of every
// kernel_launch call; each call re-zeroes them before returning.
__device__ __half   g_h0h[(size_t)MAXN * 256];   // post-aggregation, fp16
__device__ __half   g_h1h[(size_t)MAXN * 512];   // hidden layer, fp16
__device__ __half   g_Bh1[512 * 256];            // W1^T fp16: [n<512][k<256]
__device__ __half   g_Bh2[256 * 512];            // W2^T fp16: [n<256][k<512]
__device__ int      g_deg[MAXN];
__device__ int      g_rowptr[MAXN + 1];
__device__ int      g_cursor[MAXN];
__device__ int      g_esrc[MAXE];
__device__ int      g_bsum[512];
__device__ float    g_colsum[256];
__device__ float    g_colsq[256];
__device__ float    g_scale[256];
__device__ float    g_shift[256];

// ---------------- helpers ----------------------------------------------------
__device__ __forceinline__ uint32_t smem_u32(const void* p) {
    uint32_t a;
    asm("{ .reg .u64 t; cvta.to.shared.u64 t, %1; cvt.u32.u64 %0, t; }" : "=r"(a) : "l"(p));
    return a;
}

__device__ __forceinline__ uint32_t h2u(half2 h) {
    union { half2 h; uint32_t u; } cvt;
    cvt.h = h;
    return cvt.u;
}

__device__ __forceinline__ void mma_f16(float* c, const uint32_t* a, const uint32_t* b) {
    asm volatile(
        "mma.sync.aligned.m16n8k16.row.col.f32.f16.f16.f32 "
        "{%0,%1,%2,%3}, {%4,%5,%6,%7}, {%8,%9}, {%0,%1,%2,%3};"
        : "+f"(c[0]), "+f"(c[1]), "+f"(c[2]), "+f"(c[3])
        : "r"(a[0]), "r"(a[1]), "r"(a[2]), "r"(a[3]), "r"(b[0]), "r"(b[1]));
}

__device__ __forceinline__ void ldsm_x4(uint32_t& r0, uint32_t& r1, uint32_t& r2,
                                        uint32_t& r3, uint32_t addr) {
    asm volatile("ldmatrix.sync.aligned.m8n8.x4.shared.b16 {%0,%1,%2,%3}, [%4];"
                 : "=r"(r0), "=r"(r1), "=r"(r2), "=r"(r3) : "r"(addr));
}

__device__ __forceinline__ void cp16(uint32_t saddr, const void* gptr, int srcB) {
    asm volatile("cp.async.cg.shared.global [%0], [%1], 16, %2;"
                 :: "r"(saddr), "l"(gptr), "r"(srcB) : "memory");
}
__device__ __forceinline__ void cp_commit() {
    asm volatile("cp.async.commit_group;" ::: "memory");
}
template <int N>
__device__ __forceinline__ void cp_wait() {
    asm volatile("cp.async.wait_group %0;" :: "n"(N) : "memory");
}

// Per-block int64-vs-int32 sniff: int64 idx < 2^32 -> high words all zero.
__device__ __forceinline__ int block_is64(const void* idxbuf, int E) {
    __shared__ int s_bad;
    if (threadIdx.x == 0) s_bad = 0;
    __syncthreads();
    int words = E >> 1; if (words > 64) words = 64;
    if (threadIdx.x < (unsigned)words) {
        unsigned long long w = ((const unsigned long long*)idxbuf)[threadIdx.x];
        if ((w >> 32) != 0ull) atomicOr(&s_bad, 1);
    }
    __syncthreads();
    return !s_bad;
}

// ---------------- CSR aggregation (unchanged) --------------------------------
__global__ void k_hist(const void* __restrict__ dstb, int E) {
    int is64 = block_is64(dstb, E);
    int e = blockIdx.x * blockDim.x + threadIdx.x;
    if (e >= E) return;
    int d = is64 ? (int)((const long long*)dstb)[e] : ((const int*)dstb)[e];
    atomicAdd(&g_deg[d], 1);
}

__global__ __launch_bounds__(512)
void k_chunksum(int n) {
    __shared__ int sm[512];
    int t = threadIdx.x;
    int i = blockIdx.x * 512 + t;
    sm[t] = (i < n) ? g_deg[i] : 0;
    __syncthreads();
    #pragma unroll
    for (int off = 256; off > 0; off >>= 1) {
        if (t < off) sm[t] += sm[t + off];
        __syncthreads();
    }
    if (t == 0) g_bsum[blockIdx.x] = sm[0];
}

__global__ __launch_bounds__(512)
void k_scanwrite(int n) {
    __shared__ int red[512];
    __shared__ int sm[512];
    int t = threadIdx.x, b = blockIdx.x;
    int part = 0;
    for (int i = t; i < b; i += 512) part += g_bsum[i];
    red[t] = part;
    __syncthreads();
    #pragma unroll
    for (int off = 256; off > 0; off >>= 1) {
        if (t < off) red[t] += red[t + off];
        __syncthreads();
    }
    int base = red[0];

    int i = b * 512 + t;
    int v = (i < n) ? g_deg[i] : 0;
    sm[t] = v;
    __syncthreads();
    for (int off = 1; off < 512; off <<= 1) {
        int x = (t >= off) ? sm[t - off] : 0;
        __syncthreads();
        sm[t] += x;
        __syncthreads();
    }
    if (i < n) {
        int excl = base + sm[t] - v;
        g_rowptr[i] = excl;
        g_cursor[i] = excl;
        g_deg[i] = 0;                         // restore invariant
        if (i == n - 1) g_rowptr[n] = excl + v;
    }
}

__global__ void k_reorder(const void* __restrict__ srcb, const void* __restrict__ dstb, int E) {
    int is64 = block_is64(dstb, E);
    int e = blockIdx.x * blockDim.x + threadIdx.x;
    if (e >= E) return;
    int s, d;
    if (is64) {
        s = (int)((const long long*)srcb)[e];
        d = (int)((const long long*)dstb)[e];
    } else {
        s = ((const int*)srcb)[e];
        d = ((const int*)dstb)[e];
    }
    int pos = atomicAdd(&g_cursor[d], 1);
    g_esrc[pos] = s;
}

// ---------------- gather-sum, 2 warps/node, unroll 4; writes fp16 h0 ---------
__global__ __launch_bounds__(256)
void k_gather(const float4* __restrict__ x, const float* __restrict__ eps, int n) {
    int gw   = (int)((blockIdx.x * blockDim.x + threadIdx.x) >> 5);
    int lane = threadIdx.x & 31;
    int node = gw >> 1;
    if (node >= n) return;
    int col   = ((gw & 1) << 5) + lane;
    int start = g_rowptr[node], end = g_rowptr[node + 1];

    float4 a0 = make_float4(0.f, 0.f, 0.f, 0.f);
    float4 a1 = make_float4(0.f, 0.f, 0.f, 0.f);
    float4 a2 = make_float4(0.f, 0.f, 0.f, 0.f);
    float4 a3 = make_float4(0.f, 0.f, 0.f, 0.f);

    int i = start;
    for (; i + 4 <= end; i += 4) {
        int s0 = __ldg(&g_esrc[i]);
        int s1 = __ldg(&g_esrc[i + 1]);
        int s2 = __ldg(&g_esrc[i + 2]);
        int s3 = __ldg(&g_esrc[i + 3]);
        float4 v0 = __ldg(x + (size_t)s0 * D4 + col);
        float4 v1 = __ldg(x + (size_t)s1 * D4 + col);
        float4 v2 = __ldg(x + (size_t)s2 * D4 + col);
        float4 v3 = __ldg(x + (size_t)s3 * D4 + col);
        a0.x += v0.x; a0.y += v0.y; a0.z += v0.z; a0.w += v0.w;
        a1.x += v1.x; a1.y += v1.y; a1.z += v1.z; a1.w += v1.w;
        a2.x += v2.x; a2.y += v2.y; a2.z += v2.z; a2.w += v2.w;
        a3.x += v3.x; a3.y += v3.y; a3.z += v3.z; a3.w += v3.w;
    }
    for (; i < end; i++) {
        int s0 = __ldg(&g_esrc[i]);
        float4 v0 = __ldg(x + (size_t)s0 * D4 + col);
        a0.x += v0.x; a0.y += v0.y; a0.z += v0.z; a0.w += v0.w;
    }
    a0.x += a1.x + a2.x + a3.x;
    a0.y += a1.y + a2.y + a3.y;
    a0.z += a1.z + a2.z + a3.z;
    a0.w += a1.w + a2.w + a3.w;

    float sc = 1.0f + __ldg(eps);
    float4 xv = __ldg(x + (size_t)node * D4 + col);
    float r0 = fmaf(sc, xv.x, a0.x), r1 = fmaf(sc, xv.y, a0.y);
    float r2 = fmaf(sc, xv.z, a0.z), r3 = fmaf(sc, xv.w, a0.w);
    // fp16 rounding here is identical to the rounding previously done at GEMM stage
    uint2 hv = make_uint2(h2u(__floats2half2_rn(r0, r1)), h2u(__floats2half2_rn(r2, r3)));
    ((uint2*)g_h0h)[(size_t)node * D4 + col] = hv;
}

// ---------------- weight pre-transform: W[k][n] fp32 -> Bh[n][k] fp16 --------
__global__ void k_prepBH(const float* __restrict__ W, __half* __restrict__ Bh,
                         int KK, int NT) {
    int i = blockIdx.x * blockDim.x + threadIdx.x;
    if (i >= KK * NT) return;
    int k = i / NT, n = i - k * NT;
    Bh[(size_t)n * KK + k] = __float2half_rn(W[i]);
}

// ---------------- fp16 tensor-core GEMM, cp.async double-buffered ------------
// C[M,NT] = A[M,K] @ W[K,NT] + bias.  A,B fp16 in gmem. Block tile 128x128,
// BK=32, 8 warps (2x4), warp tile 64x32 m16n8k16, ldmatrix.x4, 2-stage pipeline.
// Smem rows padded to 40 halves (80B): LDSM conflict-free.
template <int K, int NT, bool RELU, bool STATS, bool OUTHALF>
__global__ __launch_bounds__(256, 2)
void k_hgemm(const __half* __restrict__ A, const __half* __restrict__ Bh,
             const float* __restrict__ bias, void* __restrict__ Cv, int M) {
    constexpr int KT = K / 32;
    constexpr int STG = 128 * 40;                 // halves per tile per stage
    __shared__ __align__(16) __half As[2 * STG];
    __shared__ __align__(16) __half Bs[2 * STG];
    __shared__ float s_sum[128];
    __shared__ float s_sq[128];

    const int tid  = threadIdx.x;
    const int warp = tid >> 5, lane = tid & 31;
    const int wm = warp >> 2, wn = warp & 3;          // 2x4 warp grid
    const int row0 = blockIdx.y * 128, n0 = blockIdx.x * 128;

    const uint32_t sAs = smem_u32(As);
    const uint32_t sBs = smem_u32(Bs);

    float acc[4][4][4];
    #pragma unroll
    for (int i = 0; i < 4; i++)
        #pragma unroll
        for (int j = 0; j < 4; j++)
            #pragma unroll
            for (int l = 0; l < 4; l++) acc[i][j][l] = 0.f;

    // ldmatrix lane->address components
    const int a_row = lane & 15, a_kb = lane >> 4;                 // A: row, k-block
    const int b_n   = (lane & 7) + ((lane >> 4) << 3);             // B: n-row
    const int b_kb  = (lane >> 3) & 1;                             // B: k-block

    // cp.async mapping: 2 chunks (16B = 8 halves) per tile per thread
    const int c0 = tid, c1 = tid + 256;            // chunk ids (512 per tile)
    const int r0c = c0 >> 2, g0 = c0 & 3;
    const int r1c = c1 >> 2, g1 = c1 & 3;
    const int szA0 = (row0 + r0c < M) ? 16 : 0;
    const int szA1 = (row0 + r1c < M) ? 16 : 0;

    auto issue = [&](int kt, int st) {
        uint32_t aBase = sAs + (st * STG) * 2;
        uint32_t bBase = sBs + (st * STG) * 2;
        cp16(aBase + (r0c * 40 + g0 * 8) * 2,
             A + (size_t)(row0 + r0c) * K + kt * 32 + g0 * 8, szA0);
        cp16(aBase + (r1c * 40 + g1 * 8) * 2,
             A + (size_t)(row0 + r1c) * K + kt * 32 + g1 * 8, szA1);
        cp16(bBase + (r0c * 40 + g0 * 8) * 2,
             Bh + (size_t)(n0 + r0c) * K + kt * 32 + g0 * 8, 16);
        cp16(bBase + (r1c * 40 + g1 * 8) * 2,
             Bh + (size_t)(n0 + r1c) * K + kt * 32 + g1 * 8, 16);
        cp_commit();
    };

    issue(0, 0);

    for (int kt = 0; kt < KT; ++kt) {
        const int st = kt & 1;
        if (kt + 1 < KT) { issue(kt + 1, st ^ 1); cp_wait<1>(); }
        else             { cp_wait<0>(); }
        __syncthreads();

        const uint32_t aStg = sAs + (st * STG) * 2;
        const uint32_t bStg = sBs + (st * STG) * 2;
        #pragma unroll
        for (int kk = 0; kk < 2; kk++) {
            uint32_t a[4][4], b[4][2];
            #pragma unroll
            for (int mf = 0; mf < 4; mf++) {
                uint32_t addr = aStg + ((wm * 64 + mf * 16 + a_row) * 40 + kk * 16 + a_kb * 8) * 2;
                ldsm_x4(a[mf][0], a[mf][1], a[mf][2], a[mf][3], addr);
            }
            #pragma unroll
            for (int p = 0; p < 2; p++) {
                uint32_t addr = bStg + ((wn * 32 + p * 16 + b_n) * 40 + kk * 16 + b_kb * 8) * 2;
                uint32_t r0, r1, r2, r3;
                ldsm_x4(r0, r1, r2, r3, addr);
                b[2 * p][0] = r0; b[2 * p][1] = r1;
                b[2 * p + 1][0] = r2; b[2 * p + 1][1] = r3;
            }
            #pragma unroll
            for (int mf = 0; mf < 4; mf++)
                #pragma unroll
                for (int nf = 0; nf < 4; nf++)
                    mma_f16(acc[mf][nf], a[mf], b[nf]);
        }
        __syncthreads();
    }

    // -------- epilogue: bias (+relu) (+BN stats) --------
    const int quad = lane >> 2, tq = lane & 3;
    float lsum[8], lsq[8];
    #pragma unroll
    for (int i = 0; i < 8; i++) { lsum[i] = 0.f; lsq[i] = 0.f; }

    #pragma unroll
    for (int mf = 0; mf < 4; mf++) {
        #pragma unroll
        for (int h = 0; h < 2; h++) {
            int row = row0 + wm * 64 + mf * 16 + quad + h * 8;
            bool ok = row < M;
            #pragma unroll
            for (int nf = 0; nf < 4; nf++) {
                int col = n0 + wn * 32 + nf * 8 + 2 * tq;
                float v0 = acc[mf][nf][2 * h + 0] + __ldg(&bias[col]);
                float v1 = acc[mf][nf][2 * h + 1] + __ldg(&bias[col + 1]);
                if (RELU) { v0 = fmaxf(v0, 0.f); v1 = fmaxf(v1, 0.f); }
                if (ok) {
                    if (OUTHALF) {
                        *(uint32_t*)((__half*)Cv + (size_t)row * NT + col) =
                            h2u(__floats2half2_rn(v0, v1));
                    } else {
                        *(float2*)((float*)Cv + (size_t)row * NT + col) = make_float2(v0, v1);
                    }
                    if (STATS) {
                        lsum[nf * 2    ] += v0; lsq[nf * 2    ] += v0 * v0;
                        lsum[nf * 2 + 1] += v1; lsq[nf * 2 + 1] += v1 * v1;
                    }
                }
            }
        }
    }

    if (STATS) {
        if (tid < 128) { s_sum[tid] = 0.f; s_sq[tid] = 0.f; }
        __syncthreads();
        #pragma unroll
        for (int nf = 0; nf < 4; nf++)
            #pragma unroll
            for (int j = 0; j < 2; j++) {
                int lc = wn * 32 + nf * 8 + 2 * tq + j;
                atomicAdd(&s_sum[lc], lsum[nf * 2 + j]);
                atomicAdd(&s_sq[lc],  lsq[nf * 2 + j]);
            }
        __syncthreads();
        if (tid < 128) {
            atomicAdd(&g_colsum[n0 + tid], s_sum[tid]);
            atomicAdd(&g_colsq[n0 + tid],  s_sq[tid]);
        }
    }
}

// ---------------- BN finalize (re-zeroes accumulators) -----------------------
__global__ void k_finalize(const float* __restrict__ gamma,
                           const float* __restrict__ beta, float invN) {
    int c = threadIdx.x;
    float mean = g_colsum[c] * invN;
    float var  = g_colsq[c] * invN - mean * mean;
    var = fmaxf(var, 0.f);
    float inv  = rsqrtf(var + 1e-5f);
    float sc   = gamma[c] * inv;
    g_scale[c] = sc;
    g_shift[c] = beta[c] - mean * sc;
    g_colsum[c] = 0.f;
    g_colsq[c]  = 0.f;
}

// ---------------- BN apply ---------------------------------------------------
__global__ void k_bn(float4* __restrict__ out, int n4) {
    const float4* sc4 = (const float4*)g_scale;
    const float4* sh4 = (const float4*)g_shift;
    for (int i = blockIdx.x * blockDim.x + threadIdx.x; i < n4; i += gridDim.x * blockDim.x) {
        int c4 = i & (D4 - 1);
        float4 sc = sc4[c4], sh = sh4[c4];
        float4 v = out[i];
        v.x = fmaf(v.x, sc.x, sh.x);
        v.y = fmaf(v.y, sc.y, sh.y);
        v.z = fmaf(v.z, sc.z, sh.z);
        v.w = fmaf(v.w, sc.w, sh.w);
        out[i] = v;
    }
}

// ---------------- launch -----------------------------------------------------
extern "C" void kernel_launch(void* const* d_in, const int* in_sizes, int n_in,
                              void* d_out, int out_size) {
    const float* x     = (const float*)d_in[0];
    const void*  src   = d_in[1];
    const void*  dst   = d_in[2];
    const float* eps   = (const float*)d_in[3];
    const float* W1    = (const float*)d_in[4];
    const float* b1    = (const float*)d_in[5];
    const float* W2    = (const float*)d_in[6];
    const float* b2    = (const float*)d_in[7];
    const float* gamma = (const float*)d_in[8];
    const float* beta  = (const float*)d_in[9];
    float* out = (float*)d_out;

    int M  = in_sizes[0] / DMODEL;
    int E  = in_sizes[1];
    int n4 = M * D4;

    void* ph0  = nullptr; cudaGetSymbolAddress(&ph0,  g_h0h);
    void* ph1  = nullptr; cudaGetSymbolAddress(&ph1,  g_h1h);
    void* pbh1 = nullptr; cudaGetSymbolAddress(&pbh1, g_Bh1);
    void* pbh2 = nullptr; cudaGetSymbolAddress(&pbh2, g_Bh2);

    int NSB = (M + 511) / 512;

    k_hist<<<(E + 255) / 256, 256>>>(dst, E);          // 0
    k_chunksum<<<NSB, 512>>>(M);                       // 1
    k_scanwrite<<<NSB, 512>>>(M);                      // 2
    k_reorder<<<(E + 255) / 256, 256>>>(src, dst, E);  // 3  <- profiled (canary)
    k_gather<<<(M * 64 + 255) / 256, 256>>>((const float4*)x, eps, M);

    k_prepBH<<<(256 * 512 + 255) / 256, 256>>>(W1, (__half*)pbh1, 256, 512);
    k_prepBH<<<(512 * 256 + 255) / 256, 256>>>(W2, (__half*)pbh2, 512, 256);

    int mt = (M + 127) / 128;
    k_hgemm<256, 512, true,  false, true ><<<dim3(4, mt), 256>>>(
        (const __half*)ph0, (const __half*)pbh1, b1, ph1, M);
    k_hgemm<512, 256, false, true,  false><<<dim3(2, mt), 256>>>(
        (const __half*)ph1, (const __half*)pbh2, b2, out, M);

    k_finalize<<<1, 256>>>(gamma, beta, 1.0f / (float)M);
    k_bn<<<2048, 256>>>((float4*)out, n4);
}

// round 11
// speedup vs baseline: 2.5380x; 1.0802x over previous
#include <cuda_runtime.h>
#include <cuda_fp16.h>
#include <cstdint>

#define DMODEL 256
#define D4     64
#define MAXN   100000
#define MAXE   1700000

// ---------------- scratch (static device globals, zero-init at load) --------
// INVARIANT: g_deg, g_colsum, g_colsq are all-zero at entry of every
// kernel_launch call; each call re-zeroes them before returning.
__device__ __half   g_xh[(size_t)MAXN * 256];    // node features, fp16
__device__ __half   g_h0h[(size_t)MAXN * 256];   // post-aggregation, fp16
__device__ __half   g_h1h[(size_t)MAXN * 512];   // hidden layer, fp16
__device__ __half   g_Bh1[512 * 256];            // W1^T fp16: [n<512][k<256]
__device__ __half   g_Bh2[256 * 512];            // W2^T fp16: [n<256][k<512]
__device__ int      g_deg[MAXN];
__device__ int      g_rowptr[MAXN + 1];
__device__ int      g_cursor[MAXN];
__device__ int      g_esrc[MAXE];
__device__ int      g_bsum[512];
__device__ float    g_colsum[256];
__device__ float    g_colsq[256];
__device__ float    g_scale[256];
__device__ float    g_shift[256];

// ---------------- helpers ----------------------------------------------------
__device__ __forceinline__ uint32_t smem_u32(const void* p) {
    uint32_t a;
    asm("{ .reg .u64 t; cvta.to.shared.u64 t, %1; cvt.u32.u64 %0, t; }" : "=r"(a) : "l"(p));
    return a;
}

__device__ __forceinline__ uint32_t h2u(half2 h) {
    union { half2 h; uint32_t u; } cvt;
    cvt.h = h;
    return cvt.u;
}

__device__ __forceinline__ float2 u2f2(uint32_t u) {
    union { uint32_t u; half2 h; } cvt;
    cvt.u = u;
    return __half22float2(cvt.h);
}

__device__ __forceinline__ void mma_f16(float* c, const uint32_t* a, const uint32_t* b) {
    asm volatile(
        "mma.sync.aligned.m16n8k16.row.col.f32.f16.f16.f32 "
        "{%0,%1,%2,%3}, {%4,%5,%6,%7}, {%8,%9}, {%0,%1,%2,%3};"
        : "+f"(c[0]), "+f"(c[1]), "+f"(c[2]), "+f"(c[3])
        : "r"(a[0]), "r"(a[1]), "r"(a[2]), "r"(a[3]), "r"(b[0]), "r"(b[1]));
}

__device__ __forceinline__ void ldsm_x4(uint32_t& r0, uint32_t& r1, uint32_t& r2,
                                        uint32_t& r3, uint32_t addr) {
    asm volatile("ldmatrix.sync.aligned.m8n8.x4.shared.b16 {%0,%1,%2,%3}, [%4];"
                 : "=r"(r0), "=r"(r1), "=r"(r2), "=r"(r3) : "r"(addr));
}

__device__ __forceinline__ void cp16(uint32_t saddr, const void* gptr, int srcB) {
    asm volatile("cp.async.cg.shared.global [%0], [%1], 16, %2;"
                 :: "r"(saddr), "l"(gptr), "r"(srcB) : "memory");
}
__device__ __forceinline__ void cp_commit() {
    asm volatile("cp.async.commit_group;" ::: "memory");
}
template <int N>
__device__ __forceinline__ void cp_wait() {
    asm volatile("cp.async.wait_group %0;" :: "n"(N) : "memory");
}

// Per-block int64-vs-int32 sniff: int64 idx < 2^32 -> high words all zero.
__device__ __forceinline__ int block_is64(const void* idxbuf, int E) {
    __shared__ int s_bad;
    if (threadIdx.x == 0) s_bad = 0;
    __syncthreads();
    int words = E >> 1; if (words > 64) words = 64;
    if (threadIdx.x < (unsigned)words) {
        unsigned long long w = ((const unsigned long long*)idxbuf)[threadIdx.x];
        if ((w >> 32) != 0ull) atomicOr(&s_bad, 1);
    }
    __syncthreads();
    return !s_bad;
}

// ---------------- CSR aggregation (unchanged) --------------------------------
__global__ void k_hist(const void* __restrict__ dstb, int E) {
    int is64 = block_is64(dstb, E);
    int e = blockIdx.x * blockDim.x + threadIdx.x;
    if (e >= E) return;
    int d = is64 ? (int)((const long long*)dstb)[e] : ((const int*)dstb)[e];
    atomicAdd(&g_deg[d], 1);
}

__global__ __launch_bounds__(512)
void k_chunksum(int n) {
    __shared__ int sm[512];
    int t = threadIdx.x;
    int i = blockIdx.x * 512 + t;
    sm[t] = (i < n) ? g_deg[i] : 0;
    __syncthreads();
    #pragma unroll
    for (int off = 256; off > 0; off >>= 1) {
        if (t < off) sm[t] += sm[t + off];
        __syncthreads();
    }
    if (t == 0) g_bsum[blockIdx.x] = sm[0];
}

__global__ __launch_bounds__(512)
void k_scanwrite(int n) {
    __shared__ int red[512];
    __shared__ int sm[512];
    int t = threadIdx.x, b = blockIdx.x;
    int part = 0;
    for (int i = t; i < b; i += 512) part += g_bsum[i];
    red[t] = part;
    __syncthreads();
    #pragma unroll
    for (int off = 256; off > 0; off >>= 1) {
        if (t < off) red[t] += red[t + off];
        __syncthreads();
    }
    int base = red[0];

    int i = b * 512 + t;
    int v = (i < n) ? g_deg[i] : 0;
    sm[t] = v;
    __syncthreads();
    for (int off = 1; off < 512; off <<= 1) {
        int x = (t >= off) ? sm[t - off] : 0;
        __syncthreads();
        sm[t] += x;
        __syncthreads();
    }
    if (i < n) {
        int excl = base + sm[t] - v;
        g_rowptr[i] = excl;
        g_cursor[i] = excl;
        g_deg[i] = 0;                         // restore invariant
        if (i == n - 1) g_rowptr[n] = excl + v;
    }
}

__global__ void k_reorder(const void* __restrict__ srcb, const void* __restrict__ dstb, int E) {
    int is64 = block_is64(dstb, E);
    int e = blockIdx.x * blockDim.x + threadIdx.x;
    if (e >= E) return;
    int s, d;
    if (is64) {
        s = (int)((const long long*)srcb)[e];
        d = (int)((const long long*)dstb)[e];
    } else {
        s = ((const int*)srcb)[e];
        d = ((const int*)dstb)[e];
    }
    int pos = atomicAdd(&g_cursor[d], 1);
    g_esrc[pos] = s;
}

// ---------------- x fp32 -> fp16 (shrinks gather working set to 51MB) --------
__global__ void k_prepX(const float4* __restrict__ x, int n4) {
    uint2* xh = (uint2*)g_xh;
    for (int i = blockIdx.x * blockDim.x + threadIdx.x; i < n4; i += gridDim.x * blockDim.x) {
        float4 v = x[i];
        xh[i] = make_uint2(h2u(__floats2half2_rn(v.x, v.y)),
                           h2u(__floats2half2_rn(v.z, v.w)));
    }
}

// ---------------- gather-sum over fp16 rows, 2 warps/node, unroll 4 ----------
__global__ __launch_bounds__(256)
void k_gather(const float* __restrict__ eps, int n) {
    int gw   = (int)((blockIdx.x * blockDim.x + threadIdx.x) >> 5);
    int lane = threadIdx.x & 31;
    int node = gw >> 1;
    if (node >= n) return;
    int col   = ((gw & 1) << 5) + lane;            // uint2 column 0..63 (4 halves)
    int start = g_rowptr[node], end = g_rowptr[node + 1];
    const uint2* xh = (const uint2*)g_xh;

    float4 a0 = make_float4(0.f, 0.f, 0.f, 0.f);
    float4 a1 = make_float4(0.f, 0.f, 0.f, 0.f);
    float4 a2 = make_float4(0.f, 0.f, 0.f, 0.f);
    float4 a3 = make_float4(0.f, 0.f, 0.f, 0.f);

    int i = start;
    for (; i + 4 <= end; i += 4) {
        int s0 = __ldg(&g_esrc[i]);
        int s1 = __ldg(&g_esrc[i + 1]);
        int s2 = __ldg(&g_esrc[i + 2]);
        int s3 = __ldg(&g_esrc[i + 3]);
        uint2 v0 = __ldg(xh + (size_t)s0 * D4 + col);
        uint2 v1 = __ldg(xh + (size_t)s1 * D4 + col);
        uint2 v2 = __ldg(xh + (size_t)s2 * D4 + col);
        uint2 v3 = __ldg(xh + (size_t)s3 * D4 + col);
        float2 f;
        f = u2f2(v0.x); a0.x += f.x; a0.y += f.y;
        f = u2f2(v0.y); a0.z += f.x; a0.w += f.y;
        f = u2f2(v1.x); a1.x += f.x; a1.y += f.y;
        f = u2f2(v1.y); a1.z += f.x; a1.w += f.y;
        f = u2f2(v2.x); a2.x += f.x; a2.y += f.y;
        f = u2f2(v2.y); a2.z += f.x; a2.w += f.y;
        f = u2f2(v3.x); a3.x += f.x; a3.y += f.y;
        f = u2f2(v3.y); a3.z += f.x; a3.w += f.y;
    }
    for (; i < end; i++) {
        int s0 = __ldg(&g_esrc[i]);
        uint2 v0 = __ldg(xh + (size_t)s0 * D4 + col);
        float2 f;
        f = u2f2(v0.x); a0.x += f.x; a0.y += f.y;
        f = u2f2(v0.y); a0.z += f.x; a0.w += f.y;
    }
    a0.x += a1.x + a2.x + a3.x;
    a0.y += a1.y + a2.y + a3.y;
    a0.z += a1.z + a2.z + a3.z;
    a0.w += a1.w + a2.w + a3.w;

    float sc = 1.0f + __ldg(eps);
    uint2 xv = __ldg(xh + (size_t)node * D4 + col);
    float2 fx0 = u2f2(xv.x), fx1 = u2f2(xv.y);
    float r0 = fmaf(sc, fx0.x, a0.x), r1 = fmaf(sc, fx0.y, a0.y);
    float r2 = fmaf(sc, fx1.x, a0.z), r3 = fmaf(sc, fx1.y, a0.w);
    uint2 hv = make_uint2(h2u(__floats2half2_rn(r0, r1)), h2u(__floats2half2_rn(r2, r3)));
    ((uint2*)g_h0h)[(size_t)node * D4 + col] = hv;
}

// ---------------- weight pre-transform: W[k][n] fp32 -> Bh[n][k] fp16 --------
__global__ void k_prepBH(const float* __restrict__ W, __half* __restrict__ Bh,
                         int KK, int NT) {
    int i = blockIdx.x * blockDim.x + threadIdx.x;
    if (i >= KK * NT) return;
    int k = i / NT, n = i - k * NT;
    Bh[(size_t)n * KK + k] = __float2half_rn(W[i]);
}

// ---------------- fp16 tensor-core GEMM, cp.async double-buffered ------------
// C[M,NT] = A[M,K] @ W[K,NT] + bias.  A,B fp16 in gmem. Block tile 128x128,
// BK=32, 8 warps (2x4), warp tile 64x32 m16n8k16, ldmatrix.x4, 2-stage pipeline.
// Smem rows padded to 40 halves (80B): LDSM conflict-free.
template <int K, int NT, bool RELU, bool STATS, bool OUTHALF>
__global__ __launch_bounds__(256, 2)
void k_hgemm(const __half* __restrict__ A, const __half* __restrict__ Bh,
             const float* __restrict__ bias, void* __restrict__ Cv, int M) {
    constexpr int KT = K / 32;
    constexpr int STG = 128 * 40;                 // halves per tile per stage
    __shared__ __align__(16) __half As[2 * STG];
    __shared__ __align__(16) __half Bs[2 * STG];
    __shared__ float s_sum[128];
    __shared__ float s_sq[128];

    const int tid  = threadIdx.x;
    const int warp = tid >> 5, lane = tid & 31;
    const int wm = warp >> 2, wn = warp & 3;          // 2x4 warp grid
    const int row0 = blockIdx.y * 128, n0 = blockIdx.x * 128;

    const uint32_t sAs = smem_u32(As);
    const uint32_t sBs = smem_u32(Bs);

    float acc[4][4][4];
    #pragma unroll
    for (int i = 0; i < 4; i++)
        #pragma unroll
        for (int j = 0; j < 4; j++)
            #pragma unroll
            for (int l = 0; l < 4; l++) acc[i][j][l] = 0.f;

    // ldmatrix lane->address components
    const int a_row = lane & 15, a_kb = lane >> 4;                 // A: row, k-block
    const int b_n   = (lane & 7) + ((lane >> 4) << 3);             // B: n-row
    const int b_kb  = (lane >> 3) & 1;                             // B: k-block

    // cp.async mapping: 2 chunks (16B = 8 halves) per tile per thread
    const int c0 = tid, c1 = tid + 256;            // chunk ids (512 per tile)
    const int r0c = c0 >> 2, g0 = c0 & 3;
    const int r1c = c1 >> 2, g1 = c1 & 3;
    const int szA0 = (row0 + r0c < M) ? 16 : 0;
    const int szA1 = (row0 + r1c < M) ? 16 : 0;

    auto issue = [&](int kt, int st) {
        uint32_t aBase = sAs + (st * STG) * 2;
        uint32_t bBase = sBs + (st * STG) * 2;
        cp16(aBase + (r0c * 40 + g0 * 8) * 2,
             A + (size_t)(row0 + r0c) * K + kt * 32 + g0 * 8, szA0);
        cp16(aBase + (r1c * 40 + g1 * 8) * 2,
             A + (size_t)(row0 + r1c) * K + kt * 32 + g1 * 8, szA1);
        cp16(bBase + (r0c * 40 + g0 * 8) * 2,
             Bh + (size_t)(n0 + r0c) * K + kt * 32 + g0 * 8, 16);
        cp16(bBase + (r1c * 40 + g1 * 8) * 2,
             Bh + (size_t)(n0 + r1c) * K + kt * 32 + g1 * 8, 16);
        cp_commit();
    };

    issue(0, 0);

    for (int kt = 0; kt < KT; ++kt) {
        const int st = kt & 1;
        if (kt + 1 < KT) { issue(kt + 1, st ^ 1); cp_wait<1>(); }
        else             { cp_wait<0>(); }
        __syncthreads();

        const uint32_t aStg = sAs + (st * STG) * 2;
        const uint32_t bStg = sBs + (st * STG) * 2;
        #pragma unroll
        for (int kk = 0; kk < 2; kk++) {
            uint32_t a[4][4], b[4][2];
            #pragma unroll
            for (int mf = 0; mf < 4; mf++) {
                uint32_t addr = aStg + ((wm * 64 + mf * 16 + a_row) * 40 + kk * 16 + a_kb * 8) * 2;
                ldsm_x4(a[mf][0], a[mf][1], a[mf][2], a[mf][3], addr);
            }
            #pragma unroll
            for (int p = 0; p < 2; p++) {
                uint32_t addr = bStg + ((wn * 32 + p * 16 + b_n) * 40 + kk * 16 + b_kb * 8) * 2;
                uint32_t r0, r1, r2, r3;
                ldsm_x4(r0, r1, r2, r3, addr);
                b[2 * p][0] = r0; b[2 * p][1] = r1;
                b[2 * p + 1][0] = r2; b[2 * p + 1][1] = r3;
            }
            #pragma unroll
            for (int mf = 0; mf < 4; mf++)
                #pragma unroll
                for (int nf = 0; nf < 4; nf++)
                    mma_f16(acc[mf][nf], a[mf], b[nf]);
        }
        __syncthreads();
    }

    // -------- epilogue: bias (+relu) (+BN stats) --------
    const int quad = lane >> 2, tq = lane & 3;
    float lsum[8], lsq[8];
    #pragma unroll
    for (int i = 0; i < 8; i++) { lsum[i] = 0.f; lsq[i] = 0.f; }

    #pragma unroll
    for (int mf = 0; mf < 4; mf++) {
        #pragma unroll
        for (int h = 0; h < 2; h++) {
            int row = row0 + wm * 64 + mf * 16 + quad + h * 8;
            bool ok = row < M;
            #pragma unroll
            for (int nf = 0; nf < 4; nf++) {
                int col = n0 + wn * 32 + nf * 8 + 2 * tq;
                float v0 = acc[mf][nf][2 * h + 0] + __ldg(&bias[col]);
                float v1 = acc[mf][nf][2 * h + 1] + __ldg(&bias[col + 1]);
                if (RELU) { v0 = fmaxf(v0, 0.f); v1 = fmaxf(v1, 0.f); }
                if (ok) {
                    if (OUTHALF) {
                        *(uint32_t*)((__half*)Cv + (size_t)row * NT + col) =
                            h2u(__floats2half2_rn(v0, v1));
                    } else {
                        *(float2*)((float*)Cv + (size_t)row * NT + col) = make_float2(v0, v1);
                    }
                    if (STATS) {
                        lsum[nf * 2    ] += v0; lsq[nf * 2    ] += v0 * v0;
                        lsum[nf * 2 + 1] += v1; lsq[nf * 2 + 1] += v1 * v1;
                    }
                }
            }
        }
    }

    if (STATS) {
        if (tid < 128) { s_sum[tid] = 0.f; s_sq[tid] = 0.f; }
        __syncthreads();
        #pragma unroll
        for (int nf = 0; nf < 4; nf++)
            #pragma unroll
            for (int j = 0; j < 2; j++) {
                int lc = wn * 32 + nf * 8 + 2 * tq + j;
                atomicAdd(&s_sum[lc], lsum[nf * 2 + j]);
                atomicAdd(&s_sq[lc],  lsq[nf * 2 + j]);
            }
        __syncthreads();
        if (tid < 128) {
            atomicAdd(&g_colsum[n0 + tid], s_sum[tid]);
            atomicAdd(&g_colsq[n0 + tid],  s_sq[tid]);
        }
    }
}

// ---------------- BN finalize (re-zeroes accumulators) -----------------------
__global__ void k_finalize(const float* __restrict__ gamma,
                           const float* __restrict__ beta, float invN) {
    int c = threadIdx.x;
    float mean = g_colsum[c] * invN;
    float var  = g_colsq[c] * invN - mean * mean;
    var = fmaxf(var, 0.f);
    float inv  = rsqrtf(var + 1e-5f);
    float sc   = gamma[c] * inv;
    g_scale[c] = sc;
    g_shift[c] = beta[c] - mean * sc;
    g_colsum[c] = 0.f;
    g_colsq[c]  = 0.f;
}

// ---------------- BN apply ---------------------------------------------------
__global__ void k_bn(float4* __restrict__ out, int n4) {
    const float4* sc4 = (const float4*)g_scale;
    const float4* sh4 = (const float4*)g_shift;
    for (int i = blockIdx.x * blockDim.x + threadIdx.x; i < n4; i += gridDim.x * blockDim.x) {
        int c4 = i & (D4 - 1);
        float4 sc = sc4[c4], sh = sh4[c4];
        float4 v = out[i];
        v.x = fmaf(v.x, sc.x, sh.x);
        v.y = fmaf(v.y, sc.y, sh.y);
        v.z = fmaf(v.z, sc.z, sh.z);
        v.w = fmaf(v.w, sc.w, sh.w);
        out[i] = v;
    }
}

// ---------------- launch -----------------------------------------------------
extern "C" void kernel_launch(void* const* d_in, const int* in_sizes, int n_in,
                              void* d_out, int out_size) {
    const float* x     = (const float*)d_in[0];
    const void*  src   = d_in[1];
    const void*  dst   = d_in[2];
    const float* eps   = (const float*)d_in[3];
    const float* W1    = (const float*)d_in[4];
    const float* b1    = (const float*)d_in[5];
    const float* W2    = (const float*)d_in[6];
    const float* b2    = (const float*)d_in[7];
    const float* gamma = (const float*)d_in[8];
    const float* beta  = (const float*)d_in[9];
    float* out = (float*)d_out;

    int M  = in_sizes[0] / DMODEL;
    int E  = in_sizes[1];
    int n4 = M * D4;

    void* ph0  = nullptr; cudaGetSymbolAddress(&ph0,  g_h0h);
    void* ph1  = nullptr; cudaGetSymbolAddress(&ph1,  g_h1h);
    void* pbh1 = nullptr; cudaGetSymbolAddress(&pbh1, g_Bh1);
    void* pbh2 = nullptr; cudaGetSymbolAddress(&pbh2, g_Bh2);

    int NSB = (M + 511) / 512;

    k_hist<<<(E + 255) / 256, 256>>>(dst, E);          // 0
    k_chunksum<<<NSB, 512>>>(M);                       // 1
    k_scanwrite<<<NSB, 512>>>(M);                      // 2
    k_reorder<<<(E + 255) / 256, 256>>>(src, dst, E);  // 3  <- profiled (canary)
    k_prepX<<<1024, 256>>>((const float4*)x, n4);      // 4
    k_gather<<<(M * 64 + 255) / 256, 256>>>(eps, M);   // 5

    k_prepBH<<<(256 * 512 + 255) / 256, 256>>>(W1, (__half*)pbh1, 256, 512);
    k_prepBH<<<(512 * 256 + 255) / 256, 256>>>(W2, (__half*)pbh2, 512, 256);

    int mt = (M + 127) / 128;
    k_hgemm<256, 512, true,  false, true ><<<dim3(4, mt), 256>>>(
        (const __half*)ph0, (const __half*)pbh1, b1, ph1, M);
    k_hgemm<512, 256, false, true,  false><<<dim3(2, mt), 256>>>(
        (const __half*)ph1, (const __half*)pbh2, b2, out, M);

    k_finalize<<<1, 256>>>(gamma, beta, 1.0f / (float)M);
    k_bn<<<2048, 256>>>((float4*)out, n4);
}

// round 14
// speedup vs baseline: 2.5969x; 1.0232x over previous
#include <cuda_runtime.h>
#include <cuda_fp16.h>
#include <cstdint>

#define DMODEL 256
#define D4     64
#define MAXN   100000
#define MAXE   1700000

// ---------------- scratch (static device globals, zero-init at load) --------
// INVARIANT: g_deg, g_colsum, g_colsq are all-zero at entry of every
// kernel_launch call; each call re-zeroes them before returning.
__device__ __half   g_xh[(size_t)MAXN * 256];    // node features, fp16
__device__ __half   g_h0h[(size_t)MAXN * 256];   // post-aggregation, fp16
__device__ __half   g_h1h[(size_t)MAXN * 512];   // hidden layer, fp16
__device__ __half   g_Bh1[512 * 256];            // W1^T fp16: [n<512][k<256]
__device__ __half   g_Bh2[256 * 512];            // W2^T fp16: [n<256][k<512]
__device__ int      g_deg[MAXN];
__device__ int      g_rowptr[MAXN + 1];
__device__ int      g_cursor[MAXN];
__device__ int      g_esrc[MAXE];
__device__ int      g_bsum[512];
__device__ float    g_colsum[256];
__device__ float    g_colsq[256];
__device__ float    g_scale[256];
__device__ float    g_shift[256];

// ---------------- helpers ----------------------------------------------------
__device__ __forceinline__ uint32_t smem_u32(const void* p) {
    uint32_t a;
    asm("{ .reg .u64 t; cvta.to.shared.u64 t, %1; cvt.u32.u64 %0, t; }" : "=r"(a) : "l"(p));
    return a;
}

__device__ __forceinline__ uint32_t h2u(half2 h) {
    union { half2 h; uint32_t u; } cvt;
    cvt.h = h;
    return cvt.u;
}

__device__ __forceinline__ float2 u2f2(uint32_t u) {
    union { uint32_t u; half2 h; } cvt;
    cvt.u = u;
    return __half22float2(cvt.h);
}

__device__ __forceinline__ void mma_f16(float* c, const uint32_t* a, const uint32_t* b) {
    asm volatile(
        "mma.sync.aligned.m16n8k16.row.col.f32.f16.f16.f32 "
        "{%0,%1,%2,%3}, {%4,%5,%6,%7}, {%8,%9}, {%0,%1,%2,%3};"
        : "+f"(c[0]), "+f"(c[1]), "+f"(c[2]), "+f"(c[3])
        : "r"(a[0]), "r"(a[1]), "r"(a[2]), "r"(a[3]), "r"(b[0]), "r"(b[1]));
}

__device__ __forceinline__ void ldsm_x4(uint32_t& r0, uint32_t& r1, uint32_t& r2,
                                        uint32_t& r3, uint32_t addr) {
    asm volatile("ldmatrix.sync.aligned.m8n8.x4.shared.b16 {%0,%1,%2,%3}, [%4];"
                 : "=r"(r0), "=r"(r1), "=r"(r2), "=r"(r3) : "r"(addr));
}

__device__ __forceinline__ void cp16(uint32_t saddr, const void* gptr, int srcB) {
    asm volatile("cp.async.cg.shared.global [%0], [%1], 16, %2;"
                 :: "r"(saddr), "l"(gptr), "r"(srcB) : "memory");
}
__device__ __forceinline__ void cp_commit() {
    asm volatile("cp.async.commit_group;" ::: "memory");
}
template <int N>
__device__ __forceinline__ void cp_wait() {
    asm volatile("cp.async.wait_group %0;" :: "n"(N) : "memory");
}

// accumulate 8 fp16 values (one uint4) into 8 fp32 accumulators
__device__ __forceinline__ void accum8(float* a, uint4 v) {
    float2 f;
    f = u2f2(v.x); a[0] += f.x; a[1] += f.y;
    f = u2f2(v.y); a[2] += f.x; a[3] += f.y;
    f = u2f2(v.z); a[4] += f.x; a[5] += f.y;
    f = u2f2(v.w); a[6] += f.x; a[7] += f.y;
}

// Per-block int64-vs-int32 sniff: int64 idx < 2^32 -> high words all zero.
__device__ __forceinline__ int block_is64(const void* idxbuf, int E) {
    __shared__ int s_bad;
    if (threadIdx.x == 0) s_bad = 0;
    __syncthreads();
    int words = E >> 1; if (words > 64) words = 64;
    if (threadIdx.x < (unsigned)words) {
        unsigned long long w = ((const unsigned long long*)idxbuf)[threadIdx.x];
        if ((w >> 32) != 0ull) atomicOr(&s_bad, 1);
    }
    __syncthreads();
    return !s_bad;
}

// ---------------- CSR aggregation (unchanged) --------------------------------
__global__ void k_hist(const void* __restrict__ dstb, int E) {
    int is64 = block_is64(dstb, E);
    int e = blockIdx.x * blockDim.x + threadIdx.x;
    if (e >= E) return;
    int d = is64 ? (int)((const long long*)dstb)[e] : ((const int*)dstb)[e];
    atomicAdd(&g_deg[d], 1);
}

__global__ __launch_bounds__(512)
void k_chunksum(int n) {
    __shared__ int sm[512];
    int t = threadIdx.x;
    int i = blockIdx.x * 512 + t;
    sm[t] = (i < n) ? g_deg[i] : 0;
    __syncthreads();
    #pragma unroll
    for (int off = 256; off > 0; off >>= 1) {
        if (t < off) sm[t] += sm[t + off];
        __syncthreads();
    }
    if (t == 0) g_bsum[blockIdx.x] = sm[0];
}

__global__ __launch_bounds__(512)
void k_scanwrite(int n) {
    __shared__ int red[512];
    __shared__ int sm[512];
    int t = threadIdx.x, b = blockIdx.x;
    int part = 0;
    for (int i = t; i < b; i += 512) part += g_bsum[i];
    red[t] = part;
    __syncthreads();
    #pragma unroll
    for (int off = 256; off > 0; off >>= 1) {
        if (t < off) red[t] += red[t + off];
        __syncthreads();
    }
    int base = red[0];

    int i = b * 512 + t;
    int v = (i < n) ? g_deg[i] : 0;
    sm[t] = v;
    __syncthreads();
    for (int off = 1; off < 512; off <<= 1) {
        int x = (t >= off) ? sm[t - off] : 0;
        __syncthreads();
        sm[t] += x;
        __syncthreads();
    }
    if (i < n) {
        int excl = base + sm[t] - v;
        g_rowptr[i] = excl;
        g_cursor[i] = excl;
        g_deg[i] = 0;                         // restore invariant
        if (i == n - 1) g_rowptr[n] = excl + v;
    }
}

__global__ void k_reorder(const void* __restrict__ srcb, const void* __restrict__ dstb, int E) {
    int is64 = block_is64(dstb, E);
    int e = blockIdx.x * blockDim.x + threadIdx.x;
    if (e >= E) return;
    int s, d;
    if (is64) {
        s = (int)((const long long*)srcb)[e];
        d = (int)((const long long*)dstb)[e];
    } else {
        s = ((const int*)srcb)[e];
        d = ((const int*)dstb)[e];
    }
    int pos = atomicAdd(&g_cursor[d], 1);
    g_esrc[pos] = s;
}

// ---------------- x fp32 -> fp16 (shrinks gather working set to 51MB) --------
__global__ void k_prepX(const float4* __restrict__ x, int n4) {
    uint2* xh = (uint2*)g_xh;
    for (int i = blockIdx.x * blockDim.x + threadIdx.x; i < n4; i += gridDim.x * blockDim.x) {
        float4 v = x[i];
        xh[i] = make_uint2(h2u(__floats2half2_rn(v.x, v.y)),
                           h2u(__floats2half2_rn(v.z, v.w)));
    }
}

// ---------------- gather-sum over fp16 rows, 1 warp/node, uint4 loads --------
// Row = 512B = 32 lanes x 16B: one LDG.128 per lane per edge, 4 edges in flight.
__global__ __launch_bounds__(256)
void k_gather(const float* __restrict__ eps, int n) {
    int node = (int)((blockIdx.x * blockDim.x + threadIdx.x) >> 5);
    int lane = threadIdx.x & 31;
    if (node >= n) return;
    int start = g_rowptr[node], end = g_rowptr[node + 1];
    const uint4* xh = (const uint4*)g_xh;    // 32 uint4 per row

    float a0[8], a1[8], a2[8], a3[8];
    #pragma unroll
    for (int j = 0; j < 8; j++) { a0[j] = 0.f; a1[j] = 0.f; a2[j] = 0.f; a3[j] = 0.f; }

    int i = start;
    for (; i + 4 <= end; i += 4) {
        int s0 = __ldg(&g_esrc[i]);
        int s1 = __ldg(&g_esrc[i + 1]);
        int s2 = __ldg(&g_esrc[i + 2]);
        int s3 = __ldg(&g_esrc[i + 3]);
        uint4 v0 = __ldg(xh + (size_t)s0 * 32 + lane);
        uint4 v1 = __ldg(xh + (size_t)s1 * 32 + lane);
        uint4 v2 = __ldg(xh + (size_t)s2 * 32 + lane);
        uint4 v3 = __ldg(xh + (size_t)s3 * 32 + lane);
        accum8(a0, v0); accum8(a1, v1); accum8(a2, v2); accum8(a3, v3);
    }
    for (; i < end; i++) {
        int s0 = __ldg(&g_esrc[i]);
        uint4 v0 = __ldg(xh + (size_t)s0 * 32 + lane);
        accum8(a0, v0);
    }
    #pragma unroll
    for (int j = 0; j < 8; j++) a0[j] += a1[j] + a2[j] + a3[j];

    float sc = 1.0f + __ldg(eps);
    uint4 xv = __ldg(xh + (size_t)node * 32 + lane);
    float xf[8];
    {
        float2 f;
        f = u2f2(xv.x); xf[0] = f.x; xf[1] = f.y;
        f = u2f2(xv.y); xf[2] = f.x; xf[3] = f.y;
        f = u2f2(xv.z); xf[4] = f.x; xf[5] = f.y;
        f = u2f2(xv.w); xf[6] = f.x; xf[7] = f.y;
    }
    #pragma unroll
    for (int j = 0; j < 8; j++) a0[j] = fmaf(sc, xf[j], a0[j]);

    uint4 hv = make_uint4(h2u(__floats2half2_rn(a0[0], a0[1])),
                          h2u(__floats2half2_rn(a0[2], a0[3])),
                          h2u(__floats2half2_rn(a0[4], a0[5])),
                          h2u(__floats2half2_rn(a0[6], a0[7])));
    ((uint4*)g_h0h)[(size_t)node * 32 + lane] = hv;
}

// ---------------- weight pre-transform: W[k][n] fp32 -> Bh[n][k] fp16 --------
__global__ void k_prepBH(const float* __restrict__ W, __half* __restrict__ Bh,
                         int KK, int NT) {
    int i = blockIdx.x * blockDim.x + threadIdx.x;
    if (i >= KK * NT) return;
    int k = i / NT, n = i - k * NT;
    Bh[(size_t)n * KK + k] = __float2half_rn(W[i]);
}

// ---------------- fp16 tensor-core GEMM, 3-stage cp.async pipeline -----------
// C[M,NT] = A[M,K] @ W[K,NT] + bias.  A,B fp16 in gmem. Block tile 128x128,
// BK=32, 8 warps (2x4), warp tile 64x32 m16n8k16, ldmatrix.x4.
// Dynamic smem: 3 stages x (A tile + B tile), rows padded to 40 halves.
// One __syncthreads per k-chunk: the top-of-loop sync proves the stage being
// overwritten (kt-1 mod 3) was fully consumed in the previous iteration.
template <int K, int NT, bool RELU, bool STATS, bool OUTHALF>
__global__ __launch_bounds__(256, 2)
void k_hgemm(const __half* __restrict__ A, const __half* __restrict__ Bh,
             const float* __restrict__ bias, void* __restrict__ Cv, int M) {
    constexpr int KT  = K / 32;
    constexpr int STG = 128 * 40;                 // halves per tile
    extern __shared__ __half sm[];                // [3][As STG | Bs STG]
    __shared__ float s_sum[128];
    __shared__ float s_sq[128];

    const int tid  = threadIdx.x;
    const int warp = tid >> 5, lane = tid & 31;
    const int wm = warp >> 2, wn = warp & 3;          // 2x4 warp grid
    const int row0 = blockIdx.y * 128, n0 = blockIdx.x * 128;

    const uint32_t sBase = smem_u32(sm);

    float acc[4][4][4];
    #pragma unroll
    for (int i = 0; i < 4; i++)
        #pragma unroll
        for (int j = 0; j < 4; j++)
            #pragma unroll
            for (int l = 0; l < 4; l++) acc[i][j][l] = 0.f;

    // ldmatrix lane->address components
    const int a_row = lane & 15, a_kb = lane >> 4;                 // A: row, k-block
    const int b_n   = (lane & 7) + ((lane >> 4) << 3);             // B: n-row
    const int b_kb  = (lane >> 3) & 1;                             // B: k-block

    // cp.async mapping: 2 chunks (16B = 8 halves) per tile per thread
    const int c0 = tid, c1 = tid + 256;            // chunk ids (512 per tile)
    const int r0c = c0 >> 2, g0 = c0 & 3;
    const int r1c = c1 >> 2, g1 = c1 & 3;
    const int szA0 = (row0 + r0c < M) ? 16 : 0;
    const int szA1 = (row0 + r1c < M) ? 16 : 0;

    auto issue = [&](int kt, int st) {
        uint32_t aBase = sBase + (st * 2 * STG) * 2;
        uint32_t bBase = aBase + STG * 2;
        cp16(aBase + (r0c * 40 + g0 * 8) * 2,
             A + (size_t)(row0 + r0c) * K + kt * 32 + g0 * 8, szA0);
        cp16(aBase + (r1c * 40 + g1 * 8) * 2,
             A + (size_t)(row0 + r1c) * K + kt * 32 + g1 * 8, szA1);
        cp16(bBase + (r0c * 40 + g0 * 8) * 2,
             Bh + (size_t)(n0 + r0c) * K + kt * 32 + g0 * 8, 16);
        cp16(bBase + (r1c * 40 + g1 * 8) * 2,
             Bh + (size_t)(n0 + r1c) * K + kt * 32 + g1 * 8, 16);
        cp_commit();
    };

    issue(0, 0);
    issue(1, 1);

    int st = 0;
    for (int kt = 0; kt < KT; ++kt) {
        if (kt < KT - 1) cp_wait<1>(); else cp_wait<0>();
        __syncthreads();
        if (kt + 2 < KT) issue(kt + 2, (st + 2) % 3);

        const uint32_t aStg = sBase + (st * 2 * STG) * 2;
        const uint32_t bStg = aStg + STG * 2;
        #pragma unroll
        for (int kk = 0; kk < 2; kk++) {
            uint32_t a[4][4], b[4][2];
            #pragma unroll
            for (int mf = 0; mf < 4; mf++) {
                uint32_t addr = aStg + ((wm * 64 + mf * 16 + a_row) * 40 + kk * 16 + a_kb * 8) * 2;
                ldsm_x4(a[mf][0], a[mf][1], a[mf][2], a[mf][3], addr);
            }
            #pragma unroll
            for (int p = 0; p < 2; p++) {
                uint32_t addr = bStg + ((wn * 32 + p * 16 + b_n) * 40 + kk * 16 + b_kb * 8) * 2;
                uint32_t r0, r1, r2, r3;
                ldsm_x4(r0, r1, r2, r3, addr);
                b[2 * p][0] = r0; b[2 * p][1] = r1;
                b[2 * p + 1][0] = r2; b[2 * p + 1][1] = r3;
            }
            #pragma unroll
            for (int mf = 0; mf < 4; mf++)
                #pragma unroll
                for (int nf = 0; nf < 4; nf++)
                    mma_f16(acc[mf][nf], a[mf], b[nf]);
        }
        st = (st + 1) % 3;
    }
    __syncthreads();

    // -------- epilogue: bias (+relu) (+BN stats) --------
    const int quad = lane >> 2, tq = lane & 3;
    float lsum[8], lsq[8];
    #pragma unroll
    for (int i = 0; i < 8; i++) { lsum[i] = 0.f; lsq[i] = 0.f; }

    #pragma unroll
    for (int mf = 0; mf < 4; mf++) {
        #pragma unroll
        for (int h = 0; h < 2; h++) {
            int row = row0 + wm * 64 + mf * 16 + quad + h * 8;
            bool ok = row < M;
            #pragma unroll
            for (int nf = 0; nf < 4; nf++) {
                int col = n0 + wn * 32 + nf * 8 + 2 * tq;
                float v0 = acc[mf][nf][2 * h + 0] + __ldg(&bias[col]);
                float v1 = acc[mf][nf][2 * h + 1] + __ldg(&bias[col + 1]);
                if (RELU) { v0 = fmaxf(v0, 0.f); v1 = fmaxf(v1, 0.f); }
                if (ok) {
                    if (OUTHALF) {
                        *(uint32_t*)((__half*)Cv + (size_t)row * NT + col) =
                            h2u(__floats2half2_rn(v0, v1));
                    } else {
                        *(float2*)((float*)Cv + (size_t)row * NT + col) = make_float2(v0, v1);
                    }
                    if (STATS) {
                        lsum[nf * 2    ] += v0; lsq[nf * 2    ] += v0 * v0;
                        lsum[nf * 2 + 1] += v1; lsq[nf * 2 + 1] += v1 * v1;
                    }
                }
            }
        }
    }

    if (STATS) {
        if (tid < 128) { s_sum[tid] = 0.f; s_sq[tid] = 0.f; }
        __syncthreads();
        #pragma unroll
        for (int nf = 0; nf < 4; nf++)
            #pragma unroll
            for (int j = 0; j < 2; j++) {
                int lc = wn * 32 + nf * 8 + 2 * tq + j;
                atomicAdd(&s_sum[lc], lsum[nf * 2 + j]);
                atomicAdd(&s_sq[lc],  lsq[nf * 2 + j]);
            }
        __syncthreads();
        if (tid < 128) {
            atomicAdd(&g_colsum[n0 + tid], s_sum[tid]);
            atomicAdd(&g_colsq[n0 + tid],  s_sq[tid]);
        }
    }
}

// ---------------- BN finalize (re-zeroes accumulators) -----------------------
__global__ void k_finalize(const float* __restrict__ gamma,
                           const float* __restrict__ beta, float invN) {
    int c = threadIdx.x;
    float mean = g_colsum[c] * invN;
    float var  = g_colsq[c] * invN - mean * mean;
    var = fmaxf(var, 0.f);
    float inv  = rsqrtf(var + 1e-5f);
    float sc   = gamma[c] * inv;
    g_scale[c] = sc;
    g_shift[c] = beta[c] - mean * sc;
    g_colsum[c] = 0.f;
    g_colsq[c]  = 0.f;
}

// ---------------- BN apply ---------------------------------------------------
__global__ void k_bn(float4* __restrict__ out, int n4) {
    const float4* sc4 = (const float4*)g_scale;
    const float4* sh4 = (const float4*)g_shift;
    for (int i = blockIdx.x * blockDim.x + threadIdx.x; i < n4; i += gridDim.x * blockDim.x) {
        int c4 = i & (D4 - 1);
        float4 sc = sc4[c4], sh = sh4[c4];
        float4 v = out[i];
        v.x = fmaf(v.x, sc.x, sh.x);
        v.y = fmaf(v.y, sc.y, sh.y);
        v.z = fmaf(v.z, sc.z, sh.z);
        v.w = fmaf(v.w, sc.w, sh.w);
        out[i] = v;
    }
}

// ---------------- launch -----------------------------------------------------
extern "C" void kernel_launch(void* const* d_in, const int* in_sizes, int n_in,
                              void* d_out, int out_size) {
    const float* x     = (const float*)d_in[0];
    const void*  src   = d_in[1];
    const void*  dst   = d_in[2];
    const float* eps   = (const float*)d_in[3];
    const float* W1    = (const float*)d_in[4];
    const float* b1    = (const float*)d_in[5];
    const float* W2    = (const float*)d_in[6];
    const float* b2    = (const float*)d_in[7];
    const float* gamma = (const float*)d_in[8];
    const float* beta  = (const float*)d_in[9];
    float* out = (float*)d_out;

    int M  = in_sizes[0] / DMODEL;
    int E  = in_sizes[1];
    int n4 = M * D4;

    void* ph0  = nullptr; cudaGetSymbolAddress(&ph0,  g_h0h);
    void* ph1  = nullptr; cudaGetSymbolAddress(&ph1,  g_h1h);
    void* pbh1 = nullptr; cudaGetSymbolAddress(&pbh1, g_Bh1);
    void* pbh2 = nullptr; cudaGetSymbolAddress(&pbh2, g_Bh2);

    const int DSMEM = 3 * 2 * 128 * 40 * 2;   // 61440 B: 3 stages x (A+B) tiles
    cudaFuncSetAttribute(k_hgemm<256, 512, true,  false, true>,
                         cudaFuncAttributeMaxDynamicSharedMemorySize, DSMEM);
    cudaFuncSetAttribute(k_hgemm<512, 256, false, true,  false>,
                         cudaFuncAttributeMaxDynamicSharedMemorySize, DSMEM);

    int NSB = (M + 511) / 512;

    k_hist<<<(E + 255) / 256, 256>>>(dst, E);          // 0
    k_chunksum<<<NSB, 512>>>(M);                       // 1
    k_scanwrite<<<NSB, 512>>>(M);                      // 2
    k_reorder<<<(E + 255) / 256, 256>>>(src, dst, E);  // 3  <- profiled (canary)
    k_prepX<<<1024, 256>>>((const float4*)x, n4);      // 4
    k_gather<<<(M * 32 + 255) / 256, 256>>>(eps, M);   // 5

    k_prepBH<<<(256 * 512 + 255) / 256, 256>>>(W1, (__half*)pbh1, 256, 512);
    k_prepBH<<<(512 * 256 + 255) / 256, 256>>>(W2, (__half*)pbh2, 512, 256);

    int mt = (M + 127) / 128;
    k_hgemm<256, 512, true,  false, true ><<<dim3(4, mt), 256, DSMEM>>>(
        (const __half*)ph0, (const __half*)pbh1, b1, ph1, M);
    k_hgemm<512, 256, false, true,  false><<<dim3(2, mt), 256, DSMEM>>>(
        (const __half*)ph1, (const __half*)pbh2, b2, out, M);

    k_finalize<<<1, 256>>>(gamma, beta, 1.0f / (float)M);
    k_bn<<<2048, 256>>>((float4*)out, n4);
}

// round 15
// speedup vs baseline: 2.8317x; 1.0904x over previous
#include <cuda_runtime.h>
#include <cuda_fp16.h>
#include <cstdint>

#define DMODEL 256
#define D4     64
#define MAXN   100000
#define MAXE   1700000

// ---------------- scratch (static device globals, zero-init at load) --------
// INVARIANT: g_deg is all-zero at entry of every call (k_scanwrite restores).
// g_colsum/g_colsq are zeroed at the TOP of each call by k_hist, accumulated
// by gemm2, consumed by k_bn -- deterministic across graph replays.
__device__ __half   g_xh[(size_t)MAXN * 256];    // node features, fp16
__device__ __half   g_h0h[(size_t)MAXN * 256];   // post-aggregation, fp16
__device__ __half   g_h1h[(size_t)MAXN * 512];   // hidden layer, fp16
__device__ __half   g_Bh1[512 * 256];            // W1^T fp16: [n<512][k<256]
__device__ __half   g_Bh2[256 * 512];            // W2^T fp16: [n<256][k<512]
__device__ int      g_deg[MAXN];
__device__ int      g_rowptr[MAXN + 1];
__device__ int      g_cursor[MAXN];
__device__ int      g_esrc[MAXE];
__device__ int      g_bsum[512];
__device__ float    g_colsum[256];
__device__ float    g_colsq[256];

// ---------------- helpers ----------------------------------------------------
__device__ __forceinline__ uint32_t smem_u32(const void* p) {
    uint32_t a;
    asm("{ .reg .u64 t; cvta.to.shared.u64 t, %1; cvt.u32.u64 %0, t; }" : "=r"(a) : "l"(p));
    return a;
}

__device__ __forceinline__ uint32_t h2u(half2 h) {
    union { half2 h; uint32_t u; } cvt;
    cvt.h = h;
    return cvt.u;
}

__device__ __forceinline__ float2 u2f2(uint32_t u) {
    union { uint32_t u; half2 h; } cvt;
    cvt.u = u;
    return __half22float2(cvt.h);
}

__device__ __forceinline__ void mma_f16(float* c, const uint32_t* a, const uint32_t* b) {
    asm volatile(
        "mma.sync.aligned.m16n8k16.row.col.f32.f16.f16.f32 "
        "{%0,%1,%2,%3}, {%4,%5,%6,%7}, {%8,%9}, {%0,%1,%2,%3};"
        : "+f"(c[0]), "+f"(c[1]), "+f"(c[2]), "+f"(c[3])
        : "r"(a[0]), "r"(a[1]), "r"(a[2]), "r"(a[3]), "r"(b[0]), "r"(b[1]));
}

__device__ __forceinline__ void ldsm_x4(uint32_t& r0, uint32_t& r1, uint32_t& r2,
                                        uint32_t& r3, uint32_t addr) {
    asm volatile("ldmatrix.sync.aligned.m8n8.x4.shared.b16 {%0,%1,%2,%3}, [%4];"
                 : "=r"(r0), "=r"(r1), "=r"(r2), "=r"(r3) : "r"(addr));
}

__device__ __forceinline__ void cp16(uint32_t saddr, const void* gptr, int srcB) {
    asm volatile("cp.async.cg.shared.global [%0], [%1], 16, %2;"
                 :: "r"(saddr), "l"(gptr), "r"(srcB) : "memory");
}
__device__ __forceinline__ void cp_commit() {
    asm volatile("cp.async.commit_group;" ::: "memory");
}
template <int N>
__device__ __forceinline__ void cp_wait() {
    asm volatile("cp.async.wait_group %0;" :: "n"(N) : "memory");
}

// accumulate 8 fp16 values (one uint4) into 8 fp32 accumulators
__device__ __forceinline__ void accum8(float* a, uint4 v) {
    float2 f;
    f = u2f2(v.x); a[0] += f.x; a[1] += f.y;
    f = u2f2(v.y); a[2] += f.x; a[3] += f.y;
    f = u2f2(v.z); a[4] += f.x; a[5] += f.y;
    f = u2f2(v.w); a[6] += f.x; a[7] += f.y;
}

// Per-block int64-vs-int32 sniff: int64 idx < 2^32 -> high words all zero.
__device__ __forceinline__ int block_is64(const void* idxbuf, int E) {
    __shared__ int s_bad;
    if (threadIdx.x == 0) s_bad = 0;
    __syncthreads();
    int words = E >> 1; if (words > 64) words = 64;
    if (threadIdx.x < (unsigned)words) {
        unsigned long long w = ((const unsigned long long*)idxbuf)[threadIdx.x];
        if ((w >> 32) != 0ull) atomicOr(&s_bad, 1);
    }
    __syncthreads();
    return !s_bad;
}

// ---------------- launch 0: histogram + prepX + zero BN accumulators ---------
__global__ void k_hist(const void* __restrict__ dstb, int E,
                       const float4* __restrict__ x, int n4) {
    if (blockIdx.x == 0 && threadIdx.x < 256) {
        g_colsum[threadIdx.x] = 0.f;
        g_colsq[threadIdx.x]  = 0.f;
    }
    int is64 = block_is64(dstb, E);
    int e = blockIdx.x * blockDim.x + threadIdx.x;
    if (e < E) {
        int d = is64 ? (int)((const long long*)dstb)[e] : ((const int*)dstb)[e];
        atomicAdd(&g_deg[d], 1);
    }
    // fused prepX: x fp32 -> fp16 (independent of histogram)
    uint2* xh = (uint2*)g_xh;
    for (int i = e; i < n4; i += gridDim.x * blockDim.x) {
        float4 v = x[i];
        xh[i] = make_uint2(h2u(__floats2half2_rn(v.x, v.y)),
                           h2u(__floats2half2_rn(v.z, v.w)));
    }
}

// ---------------- launch 1: per-block degree sums ----------------------------
__global__ __launch_bounds__(512)
void k_chunksum(int n) {
    __shared__ int sm[512];
    int t = threadIdx.x;
    int i = blockIdx.x * 512 + t;
    sm[t] = (i < n) ? g_deg[i] : 0;
    __syncthreads();
    #pragma unroll
    for (int off = 256; off > 0; off >>= 1) {
        if (t < off) sm[t] += sm[t + off];
        __syncthreads();
    }
    if (t == 0) g_bsum[blockIdx.x] = sm[0];
}

// ---------------- launch 2: scan + write rowptr/cursor + zero deg ------------
__global__ __launch_bounds__(512)
void k_scanwrite(int n) {
    __shared__ int red[512];
    __shared__ int sm[512];
    int t = threadIdx.x, b = blockIdx.x;
    int part = 0;
    for (int i = t; i < b; i += 512) part += g_bsum[i];
    red[t] = part;
    __syncthreads();
    #pragma unroll
    for (int off = 256; off > 0; off >>= 1) {
        if (t < off) red[t] += red[t + off];
        __syncthreads();
    }
    int base = red[0];

    int i = b * 512 + t;
    int v = (i < n) ? g_deg[i] : 0;
    sm[t] = v;
    __syncthreads();
    for (int off = 1; off < 512; off <<= 1) {
        int x = (t >= off) ? sm[t - off] : 0;
        __syncthreads();
        sm[t] += x;
        __syncthreads();
    }
    if (i < n) {
        int excl = base + sm[t] - v;
        g_rowptr[i] = excl;
        g_cursor[i] = excl;
        g_deg[i] = 0;                         // restore invariant
        if (i == n - 1) g_rowptr[n] = excl + v;
    }
}

// ---------------- launch 3 (canary): bucket edges by dst ---------------------
__global__ void k_reorder(const void* __restrict__ srcb, const void* __restrict__ dstb, int E) {
    int is64 = block_is64(dstb, E);
    int e = blockIdx.x * blockDim.x + threadIdx.x;
    if (e >= E) return;
    int s, d;
    if (is64) {
        s = (int)((const long long*)srcb)[e];
        d = (int)((const long long*)dstb)[e];
    } else {
        s = ((const int*)srcb)[e];
        d = ((const int*)dstb)[e];
    }
    int pos = atomicAdd(&g_cursor[d], 1);
    g_esrc[pos] = s;
}

// ---------------- launch 4: gather-sum, 1 warp/node, uint4 loads -------------
__global__ __launch_bounds__(256)
void k_gather(const float* __restrict__ eps, int n) {
    int node = (int)((blockIdx.x * blockDim.x + threadIdx.x) >> 5);
    int lane = threadIdx.x & 31;
    if (node >= n) return;
    int start = g_rowptr[node], end = g_rowptr[node + 1];
    const uint4* xh = (const uint4*)g_xh;    // 32 uint4 per row

    float a0[8], a1[8], a2[8], a3[8];
    #pragma unroll
    for (int j = 0; j < 8; j++) { a0[j] = 0.f; a1[j] = 0.f; a2[j] = 0.f; a3[j] = 0.f; }

    int i = start;
    for (; i + 4 <= end; i += 4) {
        int s0 = __ldg(&g_esrc[i]);
        int s1 = __ldg(&g_esrc[i + 1]);
        int s2 = __ldg(&g_esrc[i + 2]);
        int s3 = __ldg(&g_esrc[i + 3]);
        uint4 v0 = __ldg(xh + (size_t)s0 * 32 + lane);
        uint4 v1 = __ldg(xh + (size_t)s1 * 32 + lane);
        uint4 v2 = __ldg(xh + (size_t)s2 * 32 + lane);
        uint4 v3 = __ldg(xh + (size_t)s3 * 32 + lane);
        accum8(a0, v0); accum8(a1, v1); accum8(a2, v2); accum8(a3, v3);
    }
    for (; i < end; i++) {
        int s0 = __ldg(&g_esrc[i]);
        uint4 v0 = __ldg(xh + (size_t)s0 * 32 + lane);
        accum8(a0, v0);
    }
    #pragma unroll
    for (int j = 0; j < 8; j++) a0[j] += a1[j] + a2[j] + a3[j];

    float sc = 1.0f + __ldg(eps);
    uint4 xv = __ldg(xh + (size_t)node * 32 + lane);
    float xf[8];
    {
        float2 f;
        f = u2f2(xv.x); xf[0] = f.x; xf[1] = f.y;
        f = u2f2(xv.y); xf[2] = f.x; xf[3] = f.y;
        f = u2f2(xv.z); xf[4] = f.x; xf[5] = f.y;
        f = u2f2(xv.w); xf[6] = f.x; xf[7] = f.y;
    }
    #pragma unroll
    for (int j = 0; j < 8; j++) a0[j] = fmaf(sc, xf[j], a0[j]);

    uint4 hv = make_uint4(h2u(__floats2half2_rn(a0[0], a0[1])),
                          h2u(__floats2half2_rn(a0[2], a0[3])),
                          h2u(__floats2half2_rn(a0[4], a0[5])),
                          h2u(__floats2half2_rn(a0[6], a0[7])));
    ((uint4*)g_h0h)[(size_t)node * 32 + lane] = hv;
}

// ---------------- launch 5: both weight pre-transforms fused -----------------
// W1[256x512] -> g_Bh1[n<512][k<256];  W2[512x256] -> g_Bh2[n<256][k<512]
__global__ void k_prepBH(const float* __restrict__ W1, const float* __restrict__ W2) {
    int i = blockIdx.x * blockDim.x + threadIdx.x;
    if (i < 131072) {
        int k = i >> 9, n = i & 511;
        g_Bh1[n * 256 + k] = __float2half_rn(W1[i]);
    } else {
        int j = i - 131072;
        int k = j >> 8, n = j & 255;
        g_Bh2[n * 512 + k] = __float2half_rn(W2[j]);
    }
}

// ---------------- fp16 tensor-core GEMM, BK=64, 3-stage cp.async -------------
// C[M,NT] = A[M,K] @ W[K,NT] + bias.  A,B fp16 in gmem. Block tile 128x128,
// BK=64, 8 warps (2x4), warp tile 64x32 m16n8k16, ldmatrix.x4.
// Rows padded to 72 halves (144B = 36 words; 36r mod 32 covers all banks ->
// LDSM conflict-free). One __syncthreads per 64-K chunk; 3-stage prefetch.
template <int K, int NT, bool RELU, bool STATS, bool OUTHALF>
__global__ __launch_bounds__(256, 2)
void k_hgemm(const __half* __restrict__ A, const __half* __restrict__ Bh,
             const float* __restrict__ bias, void* __restrict__ Cv, int M) {
    constexpr int KT  = K / 64;
    constexpr int STG = 128 * 72;                 // halves per tile
    extern __shared__ __half sm[];                // [3][As STG | Bs STG]
    __shared__ float s_sum[128];
    __shared__ float s_sq[128];

    const int tid  = threadIdx.x;
    const int warp = tid >> 5, lane = tid & 31;
    const int wm = warp >> 2, wn = warp & 3;          // 2x4 warp grid
    const int row0 = blockIdx.y * 128, n0 = blockIdx.x * 128;

    const uint32_t sBase = smem_u32(sm);

    float acc[4][4][4];
    #pragma unroll
    for (int i = 0; i < 4; i++)
        #pragma unroll
        for (int j = 0; j < 4; j++)
            #pragma unroll
            for (int l = 0; l < 4; l++) acc[i][j][l] = 0.f;

    // ldmatrix lane->address components
    const int a_row = lane & 15, a_kb = lane >> 4;                 // A: row, k-block
    const int b_n   = (lane & 7) + ((lane >> 4) << 3);             // B: n-row
    const int b_kb  = (lane >> 3) & 1;                             // B: k-block

    // cp.async mapping: tile = 128 rows x 8 chunks of 16B -> 4 chunks/thread
    int rr[4], gg[4], szA[4];
    #pragma unroll
    for (int j = 0; j < 4; j++) {
        int c = tid + j * 256;
        rr[j] = c >> 3;
        gg[j] = c & 7;
        szA[j] = (row0 + rr[j] < M) ? 16 : 0;
    }

    auto issue = [&](int kt, int st) {
        uint32_t aBase = sBase + (st * 2 * STG) * 2;
        uint32_t bBase = aBase + STG * 2;
        #pragma unroll
        for (int j = 0; j < 4; j++) {
            cp16(aBase + (rr[j] * 72 + gg[j] * 8) * 2,
                 A + (size_t)(row0 + rr[j]) * K + kt * 64 + gg[j] * 8, szA[j]);
            cp16(bBase + (rr[j] * 72 + gg[j] * 8) * 2,
                 Bh + (size_t)(n0 + rr[j]) * K + kt * 64 + gg[j] * 8, 16);
        }
        cp_commit();
    };

    issue(0, 0);
    issue(1, 1);

    int st = 0;
    for (int kt = 0; kt < KT; ++kt) {
        if (kt < KT - 1) cp_wait<1>(); else cp_wait<0>();
        __syncthreads();
        if (kt + 2 < KT) issue(kt + 2, (st + 2) % 3);

        const uint32_t aStg = sBase + (st * 2 * STG) * 2;
        const uint32_t bStg = aStg + STG * 2;
        #pragma unroll
        for (int kk = 0; kk < 4; kk++) {
            uint32_t a[4][4], b[4][2];
            #pragma unroll
            for (int mf = 0; mf < 4; mf++) {
                uint32_t addr = aStg + ((wm * 64 + mf * 16 + a_row) * 72 + kk * 16 + a_kb * 8) * 2;
                ldsm_x4(a[mf][0], a[mf][1], a[mf][2], a[mf][3], addr);
            }
            #pragma unroll
            for (int p = 0; p < 2; p++) {
                uint32_t addr = bStg + ((wn * 32 + p * 16 + b_n) * 72 + kk * 16 + b_kb * 8) * 2;
                uint32_t r0, r1, r2, r3;
                ldsm_x4(r0, r1, r2, r3, addr);
                b[2 * p][0] = r0; b[2 * p][1] = r1;
                b[2 * p + 1][0] = r2; b[2 * p + 1][1] = r3;
            }
            #pragma unroll
            for (int mf = 0; mf < 4; mf++)
                #pragma unroll
                for (int nf = 0; nf < 4; nf++)
                    mma_f16(acc[mf][nf], a[mf], b[nf]);
        }
        st = (st + 1) % 3;
    }
    __syncthreads();

    // -------- epilogue: bias (+relu) (+BN stats) --------
    const int quad = lane >> 2, tq = lane & 3;
    float lsum[8], lsq[8];
    #pragma unroll
    for (int i = 0; i < 8; i++) { lsum[i] = 0.f; lsq[i] = 0.f; }

    #pragma unroll
    for (int mf = 0; mf < 4; mf++) {
        #pragma unroll
        for (int h = 0; h < 2; h++) {
            int row = row0 + wm * 64 + mf * 16 + quad + h * 8;
            bool ok = row < M;
            #pragma unroll
            for (int nf = 0; nf < 4; nf++) {
                int col = n0 + wn * 32 + nf * 8 + 2 * tq;
                float v0 = acc[mf][nf][2 * h + 0] + __ldg(&bias[col]);
                float v1 = acc[mf][nf][2 * h + 1] + __ldg(&bias[col + 1]);
                if (RELU) { v0 = fmaxf(v0, 0.f); v1 = fmaxf(v1, 0.f); }
                if (ok) {
                    if (OUTHALF) {
                        *(uint32_t*)((__half*)Cv + (size_t)row * NT + col) =
                            h2u(__floats2half2_rn(v0, v1));
                    } else {
                        *(float2*)((float*)Cv + (size_t)row * NT + col) = make_float2(v0, v1);
                    }
                    if (STATS) {
                        lsum[nf * 2    ] += v0; lsq[nf * 2    ] += v0 * v0;
                        lsum[nf * 2 + 1] += v1; lsq[nf * 2 + 1] += v1 * v1;
                    }
                }
            }
        }
    }

    if (STATS) {
        if (tid < 128) { s_sum[tid] = 0.f; s_sq[tid] = 0.f; }
        __syncthreads();
        #pragma unroll
        for (int nf = 0; nf < 4; nf++)
            #pragma unroll
            for (int j = 0; j < 2; j++) {
                int lc = wn * 32 + nf * 8 + 2 * tq + j;
                atomicAdd(&s_sum[lc], lsum[nf * 2 + j]);
                atomicAdd(&s_sq[lc],  lsq[nf * 2 + j]);
            }
        __syncthreads();
        if (tid < 128) {
            atomicAdd(&g_colsum[n0 + tid], s_sum[tid]);
            atomicAdd(&g_colsq[n0 + tid],  s_sq[tid]);
        }
    }
}

// ---------------- BN: per-block scale/shift compute + apply ------------------
__global__ __launch_bounds__(256)
void k_bn(float4* __restrict__ out, int n4,
          const float* __restrict__ gamma, const float* __restrict__ beta,
          float invN) {
    __shared__ float s_scale[256];
    __shared__ float s_shift[256];
    int t = threadIdx.x;
    {
        float mean = g_colsum[t] * invN;
        float var  = fmaxf(g_colsq[t] * invN - mean * mean, 0.f);
        float inv  = rsqrtf(var + 1e-5f);
        float sc   = gamma[t] * inv;
        s_scale[t] = sc;
        s_shift[t] = beta[t] - mean * sc;
    }
    __syncthreads();
    const float4* sc4 = (const float4*)s_scale;
    const float4* sh4 = (const float4*)s_shift;
    for (int i = blockIdx.x * blockDim.x + t; i < n4; i += gridDim.x * blockDim.x) {
        int c4 = i & (D4 - 1);
        float4 sc = sc4[c4], sh = sh4[c4];
        float4 v = out[i];
        v.x = fmaf(v.x, sc.x, sh.x);
        v.y = fmaf(v.y, sc.y, sh.y);
        v.z = fmaf(v.z, sc.z, sh.z);
        v.w = fmaf(v.w, sc.w, sh.w);
        out[i] = v;
    }
}

// ---------------- launch -----------------------------------------------------
extern "C" void kernel_launch(void* const* d_in, const int* in_sizes, int n_in,
                              void* d_out, int out_size) {
    const float* x     = (const float*)d_in[0];
    const void*  src   = d_in[1];
    const void*  dst   = d_in[2];
    const float* eps   = (const float*)d_in[3];
    const float* W1    = (const float*)d_in[4];
    const float* b1    = (const float*)d_in[5];
    const float* W2    = (const float*)d_in[6];
    const float* b2    = (const float*)d_in[7];
    const float* gamma = (const float*)d_in[8];
    const float* beta  = (const float*)d_in[9];
    float* out = (float*)d_out;

    int M  = in_sizes[0] / DMODEL;
    int E  = in_sizes[1];
    int n4 = M * D4;

    void* ph0  = nullptr; cudaGetSymbolAddress(&ph0,  g_h0h);
    void* ph1  = nullptr; cudaGetSymbolAddress(&ph1,  g_h1h);
    void* pbh1 = nullptr; cudaGetSymbolAddress(&pbh1, g_Bh1);
    void* pbh2 = nullptr; cudaGetSymbolAddress(&pbh2, g_Bh2);

    const int DSMEM = 3 * 2 * 128 * 72 * 2;   // 110592 B: 3 stages x (A+B) tiles
    cudaFuncSetAttribute(k_hgemm<256, 512, true,  false, true>,
                         cudaFuncAttributeMaxDynamicSharedMemorySize, DSMEM);
    cudaFuncSetAttribute(k_hgemm<512, 256, false, true,  false>,
                         cudaFuncAttributeMaxDynamicSharedMemorySize, DSMEM);

    int NSB = (M + 511) / 512;

    k_hist<<<(E + 255) / 256, 256>>>(dst, E, (const float4*)x, n4);   // 0
    k_chunksum<<<NSB, 512>>>(M);                                      // 1
    k_scanwrite<<<NSB, 512>>>(M);                                     // 2
    k_reorder<<<(E + 255) / 256, 256>>>(src, dst, E);                 // 3 canary
    k_gather<<<(M * 32 + 255) / 256, 256>>>(eps, M);                  // 4
    k_prepBH<<<1024, 256>>>(W1, W2);                                  // 5

    int mt = (M + 127) / 128;
    k_hgemm<256, 512, true,  false, true ><<<dim3(4, mt), 256, DSMEM>>>(
        (const __half*)ph0, (const __half*)pbh1, b1, ph1, M);         // 6
    k_hgemm<512, 256, false, true,  false><<<dim3(2, mt), 256, DSMEM>>>(
        (const __half*)ph1, (const __half*)pbh2, b2, out, M);         // 7

    k_bn<<<2048, 256>>>((float4*)out, n4, gamma, beta, 1.0f / (float)M);  // 8
}